// round 1
// baseline (speedup 1.0000x reference)
#include <cuda_runtime.h>
#include <math.h>

// ---------------- problem constants ----------------
constexpr int Tn  = 2048;
constexpr int Dn  = 1024;
constexpr int Hn  = 16;
constexpr int KVn = 8;
constexpr int HDn = 128;
constexpr int FFn = 3072;
constexpr int Ln  = 5;
constexpr float EPSf = 1e-6f;

// ---------------- scratch (device globals; no allocs allowed) ----------------
__device__ float g_h [Tn * Dn];
__device__ float g_x [Tn * Dn];
__device__ float g_q [Tn * Hn * HDn];
__device__ float g_ao[Tn * Hn * HDn];
__device__ float g_kt[Tn * KVn * HDn];
__device__ float g_vt[Tn * KVn * HDn];
__device__ float g_gate[Tn * FFn];
__device__ float g_up  [Tn * FFn];
__device__ float g_cos[Tn * 64];
__device__ float g_sin[Tn * 64];

// ---------------- RoPE tables (match JAX fp32 math) ----------------
__global__ void rope_tables_kernel() {
    int t = blockIdx.x;
    int j = threadIdx.x;          // 0..63
    float inv = 1.0f / powf(1.0e6f, (float)j * (1.0f / 64.0f));
    float ang = (float)t * inv;
    g_cos[t * 64 + j] = cosf(ang);
    g_sin[t * 64 + j] = sinf(ang);
}

// ---------------- RMSNorm over D=1024 rows ----------------
__global__ void rms_rows_kernel(const float* __restrict__ in,
                                const float* __restrict__ w,
                                float* __restrict__ out) {
    int t = blockIdx.x;
    const float4* ip = (const float4*)(in + (size_t)t * Dn);
    const float4* wp = (const float4*)w;
    float4 v = ip[threadIdx.x];
    float s = v.x * v.x + v.y * v.y + v.z * v.z + v.w * v.w;
#pragma unroll
    for (int off = 16; off; off >>= 1) s += __shfl_xor_sync(0xffffffffu, s, off);
    __shared__ float ws[8];
    if ((threadIdx.x & 31) == 0) ws[threadIdx.x >> 5] = s;
    __syncthreads();
    float tot = 0.f;
#pragma unroll
    for (int i = 0; i < 8; i++) tot += ws[i];
    float r = rsqrtf(tot * (1.0f / (float)Dn) + EPSf);
    float4 wv = wp[threadIdx.x];
    float4 o = make_float4(v.x * r * wv.x, v.y * r * wv.y, v.z * r * wv.z, v.w * r * wv.w);
    ((float4*)(out + (size_t)t * Dn))[threadIdx.x] = o;
}

// ---------------- per-head RMSNorm (HD=128) + RoPE ----------------
// in: [T][NH][HD]; out: transposed ? [NH][T][HD] : [T][NH][HD]
__global__ void qknorm_rope_kernel(const float* __restrict__ in,
                                   float* __restrict__ out,
                                   const float* __restrict__ w,
                                   int NH, int transposed) {
    int t = blockIdx.x, h = blockIdx.y, d = threadIdx.x;   // 128 threads
    const float* row = in + ((size_t)t * NH + h) * HDn;
    float v = row[d];
    float s = v * v;
#pragma unroll
    for (int off = 16; off; off >>= 1) s += __shfl_xor_sync(0xffffffffu, s, off);
    __shared__ float ws[4];
    if ((d & 31) == 0) ws[d >> 5] = s;
    __syncthreads();
    float tot = ws[0] + ws[1] + ws[2] + ws[3];
    float r = rsqrtf(tot * (1.0f / (float)HDn) + EPSf);
    float xn = v * r * w[d];
    __shared__ float sh[128];
    sh[d] = xn;
    __syncthreads();
    float other = (d < 64) ? -sh[d + 64] : sh[d - 64];
    int j = d & 63;
    float c = g_cos[t * 64 + j];
    float sn = g_sin[t * 64 + j];
    float o = xn * c + other * sn;
    size_t oidx = transposed ? (((size_t)h * Tn + t) * HDn + d)
                             : (((size_t)t * NH + h) * HDn + d);
    out[oidx] = o;
}

// ---------------- V transpose [T][KV][HD] -> [KV][T][HD] ----------------
__global__ void v_transpose_kernel(const float* __restrict__ in, float* __restrict__ out) {
    int idx = blockIdx.x * blockDim.x + threadIdx.x;  // over output
    int kv  = idx / (Tn * HDn);
    int rem = idx - kv * (Tn * HDn);
    int t   = rem / HDn;
    int d   = rem - t * HDn;
    out[idx] = in[((size_t)t * KVn + kv) * HDn + d];
}

// ---------------- silu(g)*u in place ----------------
__global__ void silu_mul_kernel(float* __restrict__ g, const float* __restrict__ u, int n) {
    int idx = blockIdx.x * blockDim.x + threadIdx.x;
    if (idx < n) {
        float gv = g[idx];
        float sv = gv / (1.0f + expf(-gv));
        g[idx] = sv * u[idx];
    }
}

// ---------------- generic SGEMM NT: C[M,N] = A[M,K] * B[N,K]^T ----------------
// M,N multiples of 64, K multiple of 16.
template <int ADD>
__global__ __launch_bounds__(256) void sgemm_nt_kernel(const float* __restrict__ A,
                                                       const float* __restrict__ B,
                                                       float* __restrict__ C,
                                                       int M, int N, int K) {
    __shared__ float Ast[16 * 65];
    __shared__ float Bst[16 * 65];
    const int tid = threadIdx.x;
    const int tx = tid & 15, ty = tid >> 4;
    const int m0 = blockIdx.y * 64, n0 = blockIdx.x * 64;
    float acc[4][4] = {};
    const int lrow = tid >> 2, lc4 = tid & 3;
    const float* Ap = A + (size_t)(m0 + lrow) * K + lc4 * 4;
    const float* Bp = B + (size_t)(n0 + lrow) * K + lc4 * 4;
    for (int kt = 0; kt < K; kt += 16) {
        float4 av = *(const float4*)(Ap + kt);
        float4 bv = *(const float4*)(Bp + kt);
        int dd = lc4 * 4;
        Ast[(dd + 0) * 65 + lrow] = av.x;
        Ast[(dd + 1) * 65 + lrow] = av.y;
        Ast[(dd + 2) * 65 + lrow] = av.z;
        Ast[(dd + 3) * 65 + lrow] = av.w;
        Bst[(dd + 0) * 65 + lrow] = bv.x;
        Bst[(dd + 1) * 65 + lrow] = bv.y;
        Bst[(dd + 2) * 65 + lrow] = bv.z;
        Bst[(dd + 3) * 65 + lrow] = bv.w;
        __syncthreads();
#pragma unroll
        for (int kk = 0; kk < 16; ++kk) {
            float a[4], b[4];
#pragma unroll
            for (int i = 0; i < 4; i++) a[i] = Ast[kk * 65 + ty + 16 * i];
#pragma unroll
            for (int j = 0; j < 4; j++) b[j] = Bst[kk * 65 + tx + 16 * j];
#pragma unroll
            for (int i = 0; i < 4; i++)
#pragma unroll
                for (int j = 0; j < 4; j++) acc[i][j] = fmaf(a[i], b[j], acc[i][j]);
        }
        __syncthreads();
    }
#pragma unroll
    for (int i = 0; i < 4; i++)
#pragma unroll
        for (int j = 0; j < 4; j++) {
            size_t idx = (size_t)(m0 + ty + 16 * i) * N + (n0 + tx + 16 * j);
            if (ADD) C[idx] += acc[i][j];
            else C[idx] = acc[i][j];
        }
}

// ---------------- flash attention (fp32, causal, GQA G=2) ----------------
// Q: [T][H][HD]; Kh/Vh: per-layer [KV][T][HD]; O: [T][H*HD]
constexpr int ATTN_SMEM = (2 * 128 * 65 + 64 * 65) * 4;  // 83200 bytes

__global__ __launch_bounds__(256) void attn_kernel(const float* __restrict__ Q,
                                                   const float* __restrict__ Kb,
                                                   const float* __restrict__ Vb,
                                                   float* __restrict__ O) {
    extern __shared__ float sm[];
    float* sQ = sm;                  // [128][65] Q^T (d-major), pre-scaled
    float* sK = sm + 128 * 65;       // K^T [128][65]  /  V natural [64][128] (union)
    float* sP = sm + 2 * 128 * 65;   // P^T [64][65]
    const int h = blockIdx.y;
    const int qt0 = blockIdx.x * 64;
    const int kv = h >> 1;  // G = H/KV = 2
    const float scale = 0.0883883476483184f;  // 1/sqrt(128)
    const int tid = threadIdx.x, tx = tid & 15, ty = tid >> 4;

    // load Q tile transposed + scaled
    const float* qbase = Q + (size_t)qt0 * (Hn * HDn) + (size_t)h * HDn;
#pragma unroll
    for (int r = 0; r < 8; ++r) {
        int idx = tid + r * 256;
        int row = idx >> 5, c4 = idx & 31;
        float4 v = *(const float4*)(qbase + (size_t)row * (Hn * HDn) + c4 * 4);
        int dd = c4 * 4;
        sQ[(dd + 0) * 65 + row] = v.x * scale;
        sQ[(dd + 1) * 65 + row] = v.y * scale;
        sQ[(dd + 2) * 65 + row] = v.z * scale;
        sQ[(dd + 3) * 65 + row] = v.w * scale;
    }

    float m[4], l[4], o[4][8];
#pragma unroll
    for (int i = 0; i < 4; i++) {
        m[i] = -1e30f; l[i] = 0.f;
#pragma unroll
        for (int j = 0; j < 8; j++) o[i][j] = 0.f;
    }

    const float* Kh = Kb + (size_t)kv * Tn * HDn;
    const float* Vh = Vb + (size_t)kv * Tn * HDn;
    const int nkt = (qt0 >> 6) + 1;

    for (int kt = 0; kt < nkt; ++kt) {
        const int kt0 = kt << 6;
        __syncthreads();  // prior P@V reads of sK done; also covers sQ on first iter path
        // load K tile transposed
#pragma unroll
        for (int r = 0; r < 8; ++r) {
            int idx = tid + r * 256;
            int row = idx >> 5, c4 = idx & 31;
            float4 v = *(const float4*)(Kh + (size_t)(kt0 + row) * HDn + c4 * 4);
            int dd = c4 * 4;
            sK[(dd + 0) * 65 + row] = v.x;
            sK[(dd + 1) * 65 + row] = v.y;
            sK[(dd + 2) * 65 + row] = v.z;
            sK[(dd + 3) * 65 + row] = v.w;
        }
        __syncthreads();

        // S = (Q*scale) @ K^T  (64x64)
        float s[4][4] = {};
#pragma unroll 4
        for (int d = 0; d < 128; ++d) {
            float qa[4], ka[4];
#pragma unroll
            for (int i = 0; i < 4; i++) qa[i] = sQ[d * 65 + ty + 16 * i];
#pragma unroll
            for (int j = 0; j < 4; j++) ka[j] = sK[d * 65 + tx + 16 * j];
#pragma unroll
            for (int i = 0; i < 4; i++)
#pragma unroll
                for (int j = 0; j < 4; j++) s[i][j] = fmaf(qa[i], ka[j], s[i][j]);
        }
        // causal mask on diagonal tile
        if (kt == nkt - 1) {
#pragma unroll
            for (int i = 0; i < 4; i++)
#pragma unroll
                for (int j = 0; j < 4; j++)
                    if (kt0 + tx + 16 * j > qt0 + ty + 16 * i) s[i][j] = -1e30f;
        }
        // online softmax (rows shared across 16 lanes with same ty)
#pragma unroll
        for (int i = 0; i < 4; i++) {
            float rm = fmaxf(fmaxf(s[i][0], s[i][1]), fmaxf(s[i][2], s[i][3]));
#pragma unroll
            for (int off = 8; off; off >>= 1)
                rm = fmaxf(rm, __shfl_xor_sync(0xffffffffu, rm, off, 16));
            float mn = fmaxf(m[i], rm);
            float corr = expf(m[i] - mn);
            m[i] = mn;
            float su = 0.f;
#pragma unroll
            for (int j = 0; j < 4; j++) {
                s[i][j] = expf(s[i][j] - mn);
                su += s[i][j];
            }
#pragma unroll
            for (int off = 8; off; off >>= 1)
                su += __shfl_xor_sync(0xffffffffu, su, off, 16);
            l[i] = l[i] * corr + su;
#pragma unroll
            for (int j = 0; j < 8; j++) o[i][j] *= corr;
        }
        // stage P^T
#pragma unroll
        for (int i = 0; i < 4; i++)
#pragma unroll
            for (int j = 0; j < 4; j++)
                sP[(tx + 16 * j) * 65 + (ty + 16 * i)] = s[i][j];
        __syncthreads();  // P visible; all sK reads done

        // load V tile (natural layout, overwrites sK)
#pragma unroll
        for (int r = 0; r < 8; ++r) {
            int idx = tid + r * 256;
            int row = idx >> 5, c4 = idx & 31;
            ((float4*)sK)[row * 32 + c4] =
                *(const float4*)(Vh + (size_t)(kt0 + row) * HDn + c4 * 4);
        }
        __syncthreads();

        // O += P @ V
#pragma unroll 4
        for (int kk = 0; kk < 64; ++kk) {
            float pv[4], vv[8];
#pragma unroll
            for (int i = 0; i < 4; i++) pv[i] = sP[kk * 65 + ty + 16 * i];
#pragma unroll
            for (int j = 0; j < 8; j++) vv[j] = sK[kk * 128 + tx + 16 * j];
#pragma unroll
            for (int i = 0; i < 4; i++)
#pragma unroll
                for (int j = 0; j < 8; j++) o[i][j] = fmaf(pv[i], vv[j], o[i][j]);
        }
    }

    // epilogue: O[t][h*HD + d], layout (T, H*HD)
#pragma unroll
    for (int i = 0; i < 4; i++) {
        float inv = 1.0f / l[i];
        int trow = qt0 + ty + 16 * i;
#pragma unroll
        for (int j = 0; j < 8; j++)
            O[(size_t)trow * (Hn * HDn) + h * HDn + tx + 16 * j] = o[i][j] * inv;
    }
}

// ---------------- host orchestration ----------------
extern "C" void kernel_launch(void* const* d_in, const int* in_sizes, int n_in,
                              void* d_out, int out_size) {
    const float* emb = (const float*)d_in[0];
    const float* ln1 = (const float*)d_in[1];
    const float* qw  = (const float*)d_in[2];
    const float* kw  = (const float*)d_in[3];
    const float* vw  = (const float*)d_in[4];
    const float* qn  = (const float*)d_in[5];
    const float* kn  = (const float*)d_in[6];
    const float* ow  = (const float*)d_in[7];
    const float* ln2 = (const float*)d_in[8];
    const float* gw  = (const float*)d_in[9];
    const float* uw  = (const float*)d_in[10];
    const float* dw  = (const float*)d_in[11];
    const float* nw  = (const float*)d_in[12];

    float* out  = (float*)d_out;
    float* keys = out + (size_t)Tn * Dn;
    float* vals = keys + (size_t)Ln * KVn * Tn * HDn;

    float *ph, *px, *pq, *pao, *pkt, *pvt, *pg, *pu;
    cudaGetSymbolAddress((void**)&ph,  g_h);
    cudaGetSymbolAddress((void**)&px,  g_x);
    cudaGetSymbolAddress((void**)&pq,  g_q);
    cudaGetSymbolAddress((void**)&pao, g_ao);
    cudaGetSymbolAddress((void**)&pkt, g_kt);
    cudaGetSymbolAddress((void**)&pvt, g_vt);
    cudaGetSymbolAddress((void**)&pg,  g_gate);
    cudaGetSymbolAddress((void**)&pu,  g_up);

    cudaFuncSetAttribute(attn_kernel, cudaFuncAttributeMaxDynamicSharedMemorySize, ATTN_SMEM);

    cudaMemcpyAsync(ph, emb, sizeof(float) * Tn * Dn, cudaMemcpyDeviceToDevice);
    rope_tables_kernel<<<Tn, 64>>>();

    for (int i = 0; i < Ln; ++i) {
        // x = rms(h, ln1)
        rms_rows_kernel<<<Tn, 256>>>(ph, ln1 + (size_t)i * Dn, px);
        // q, k, v projections
        sgemm_nt_kernel<0><<<dim3((Hn * HDn) / 64, Tn / 64), 256>>>(
            px, qw + (size_t)i * (Hn * HDn) * Dn, pq, Tn, Hn * HDn, Dn);
        sgemm_nt_kernel<0><<<dim3((KVn * HDn) / 64, Tn / 64), 256>>>(
            px, kw + (size_t)i * (KVn * HDn) * Dn, pkt, Tn, KVn * HDn, Dn);
        sgemm_nt_kernel<0><<<dim3((KVn * HDn) / 64, Tn / 64), 256>>>(
            px, vw + (size_t)i * (KVn * HDn) * Dn, pvt, Tn, KVn * HDn, Dn);

        float* klayer = keys + (size_t)i * KVn * Tn * HDn;
        float* vlayer = vals + (size_t)i * KVn * Tn * HDn;

        // q-norm + rope (in place); k-norm + rope (transposed into output keys)
        qknorm_rope_kernel<<<dim3(Tn, Hn), 128>>>(pq, pq, qn + (size_t)i * HDn, Hn, 0);
        qknorm_rope_kernel<<<dim3(Tn, KVn), 128>>>(pkt, klayer, kn + (size_t)i * HDn, KVn, 1);
        v_transpose_kernel<<<(Tn * KVn * HDn) / 256, 256>>>(pvt, vlayer);

        // attention
        attn_kernel<<<dim3(Tn / 64, Hn), 256, ATTN_SMEM>>>(pq, klayer, vlayer, pao);

        // h += attn_out @ o_w^T
        sgemm_nt_kernel<1><<<dim3(Dn / 64, Tn / 64), 256>>>(
            pao, ow + (size_t)i * Dn * (Hn * HDn), ph, Tn, Dn, Hn * HDn);

        // MLP
        rms_rows_kernel<<<Tn, 256>>>(ph, ln2 + (size_t)i * Dn, px);
        sgemm_nt_kernel<0><<<dim3(FFn / 64, Tn / 64), 256>>>(
            px, gw + (size_t)i * FFn * Dn, pg, Tn, FFn, Dn);
        sgemm_nt_kernel<0><<<dim3(FFn / 64, Tn / 64), 256>>>(
            px, uw + (size_t)i * FFn * Dn, pu, Tn, FFn, Dn);
        silu_mul_kernel<<<(Tn * FFn) / 256, 256>>>(pg, pu, Tn * FFn);
        sgemm_nt_kernel<1><<<dim3(Dn / 64, Tn / 64), 256>>>(
            pg, dw + (size_t)i * Dn * FFn, ph, Tn, Dn, FFn);
    }

    // hs = rms(h, norm_w)
    rms_rows_kernel<<<Tn, 256>>>(ph, nw, out);
}

// round 2
// speedup vs baseline: 2.4573x; 2.4573x over previous
#include <cuda_runtime.h>
#include <math.h>
#include <stdint.h>

// ---------------- problem constants ----------------
constexpr int Tn  = 2048;
constexpr int Dn  = 1024;
constexpr int Hn  = 16;
constexpr int KVn = 8;
constexpr int HDn = 128;
constexpr int FFn = 3072;
constexpr int Ln  = 5;
constexpr float EPSf = 1e-6f;

// ---------------- scratch (device globals; no allocs allowed) ----------------
__device__ float g_h [Tn * Dn];
__device__ float g_x [Tn * Dn];
__device__ float g_q [Tn * Hn * HDn];
__device__ float g_ao[Tn * Hn * HDn];
__device__ float g_kt[Tn * KVn * HDn];
__device__ float g_vt[Tn * KVn * HDn];
__device__ float g_gate[Tn * FFn];
__device__ float g_up  [Tn * FFn];
__device__ float g_cos[Tn * 64];
__device__ float g_sin[Tn * 64];

// ---------------- PTX helpers ----------------
__device__ __forceinline__ uint32_t sptr(const void* p) {
    return (uint32_t)__cvta_generic_to_shared(p);
}
__device__ __forceinline__ uint32_t f2tf(float f) {
    uint32_t u;
    asm("cvt.rna.tf32.f32 %0, %1;" : "=r"(u) : "f"(f));
    return u;
}
__device__ __forceinline__ void ldm_x4(uint32_t* r, uint32_t addr) {
    asm volatile("ldmatrix.sync.aligned.m8n8.x4.shared.b16 {%0,%1,%2,%3}, [%4];"
                 : "=r"(r[0]), "=r"(r[1]), "=r"(r[2]), "=r"(r[3]) : "r"(addr));
}
__device__ __forceinline__ void mma_tf32(float* c, const uint32_t* a, const uint32_t* b) {
    asm volatile("mma.sync.aligned.m16n8k8.row.col.f32.tf32.tf32.f32 "
                 "{%0,%1,%2,%3}, {%4,%5,%6,%7}, {%8,%9}, {%0,%1,%2,%3};"
                 : "+f"(c[0]), "+f"(c[1]), "+f"(c[2]), "+f"(c[3])
                 : "r"(a[0]), "r"(a[1]), "r"(a[2]), "r"(a[3]), "r"(b[0]), "r"(b[1]));
}

// ---------------- RoPE tables (match JAX fp32 math) ----------------
__global__ void rope_tables_kernel() {
    int t = blockIdx.x;
    int j = threadIdx.x;          // 0..63
    float inv = 1.0f / powf(1.0e6f, (float)j * (1.0f / 64.0f));
    float ang = (float)t * inv;
    g_cos[t * 64 + j] = cosf(ang);
    g_sin[t * 64 + j] = sinf(ang);
}

// ---------------- RMSNorm over D=1024 rows ----------------
__global__ void rms_rows_kernel(const float* __restrict__ in,
                                const float* __restrict__ w,
                                float* __restrict__ out) {
    int t = blockIdx.x;
    const float4* ip = (const float4*)(in + (size_t)t * Dn);
    const float4* wp = (const float4*)w;
    float4 v = ip[threadIdx.x];
    float s = v.x * v.x + v.y * v.y + v.z * v.z + v.w * v.w;
#pragma unroll
    for (int off = 16; off; off >>= 1) s += __shfl_xor_sync(0xffffffffu, s, off);
    __shared__ float ws[8];
    if ((threadIdx.x & 31) == 0) ws[threadIdx.x >> 5] = s;
    __syncthreads();
    float tot = 0.f;
#pragma unroll
    for (int i = 0; i < 8; i++) tot += ws[i];
    float r = rsqrtf(tot * (1.0f / (float)Dn) + EPSf);
    float4 wv = wp[threadIdx.x];
    float4 o = make_float4(v.x * r * wv.x, v.y * r * wv.y, v.z * r * wv.z, v.w * r * wv.w);
    ((float4*)(out + (size_t)t * Dn))[threadIdx.x] = o;
}

// ---------------- per-head RMSNorm (HD=128) + RoPE ----------------
__global__ void qknorm_rope_kernel(const float* __restrict__ in,
                                   float* __restrict__ out,
                                   const float* __restrict__ w,
                                   int NH, int transposed) {
    int t = blockIdx.x, h = blockIdx.y, d = threadIdx.x;   // 128 threads
    const float* row = in + ((size_t)t * NH + h) * HDn;
    float v = row[d];
    float s = v * v;
#pragma unroll
    for (int off = 16; off; off >>= 1) s += __shfl_xor_sync(0xffffffffu, s, off);
    __shared__ float ws[4];
    if ((d & 31) == 0) ws[d >> 5] = s;
    __syncthreads();
    float tot = ws[0] + ws[1] + ws[2] + ws[3];
    float r = rsqrtf(tot * (1.0f / (float)HDn) + EPSf);
    float xn = v * r * w[d];
    __shared__ float sh[128];
    sh[d] = xn;
    __syncthreads();
    float other = (d < 64) ? -sh[d + 64] : sh[d - 64];
    int j = d & 63;
    float c = g_cos[t * 64 + j];
    float sn = g_sin[t * 64 + j];
    float o = xn * c + other * sn;
    size_t oidx = transposed ? (((size_t)h * Tn + t) * HDn + d)
                             : (((size_t)t * NH + h) * HDn + d);
    out[oidx] = o;
}

// ---------------- V transpose [T][KV][HD] -> [KV][T][HD] ----------------
__global__ void v_transpose_kernel(const float* __restrict__ in, float* __restrict__ out) {
    int idx = blockIdx.x * blockDim.x + threadIdx.x;
    int kv  = idx / (Tn * HDn);
    int rem = idx - kv * (Tn * HDn);
    int t   = rem / HDn;
    int d   = rem - t * HDn;
    out[idx] = in[((size_t)t * KVn + kv) * HDn + d];
}

// ---------------- silu(g)*u in place ----------------
__global__ void silu_mul_kernel(float* __restrict__ g, const float* __restrict__ u, int n) {
    int idx = blockIdx.x * blockDim.x + threadIdx.x;
    if (idx < n) {
        float gv = g[idx];
        float sv = gv / (1.0f + expf(-gv));
        g[idx] = sv * u[idx];
    }
}

// ---------------- TF32 tensor-core GEMM NT: C[M,N] = A[M,K] * B[N,K]^T ----------------
// BM=BN=128, BK=32, 256 threads, 8 warps (4M x 2N), warp tile 32x64.
constexpr int GBM = 128, GBN = 128, GBK = 32, GPAD = 4, GLDS = GBK + GPAD;  // 36
constexpr int GSTAGE = GBM * GLDS;                                          // words
constexpr int GEMM_SMEM = 4 * GSTAGE * 4;                                   // 73728 B

template <int ADD>
__global__ __launch_bounds__(256) void mma_nt_kernel(const float* __restrict__ A,
                                                     const float* __restrict__ B,
                                                     float* __restrict__ C,
                                                     int M, int N, int K) {
    extern __shared__ float smem[];
    float* sA = smem;                 // [2][GSTAGE]
    float* sB = smem + 2 * GSTAGE;    // [2][GSTAGE]

    const int tid = threadIdx.x, lane = tid & 31, wid = tid >> 5;
    const int wm = wid & 3, wn = wid >> 2;
    const int m0 = blockIdx.y * GBM, n0 = blockIdx.x * GBN;

    // staging: 8 threads per row, each thread 4 rows (stride 32)
    const int sr = tid >> 3;
    const int sc = (tid & 7) * 4;
    const float* Ag = A + (size_t)(m0 + sr) * K + sc;
    const float* Bg = B + (size_t)(n0 + sr) * K + sc;

    float acc[2][8][4];
#pragma unroll
    for (int i = 0; i < 2; i++)
#pragma unroll
        for (int j = 0; j < 8; j++)
#pragma unroll
            for (int q = 0; q < 4; q++) acc[i][j][q] = 0.f;

    // ldmatrix lane addressing
    const int grp = lane >> 3, lr = lane & 7;
    const int a_row = wm * 32 + (grp & 1) * 8 + lr;   // + mt*16
    const int a_col = (grp >> 1) * 4;                 // + ks*8
    const int b_row = wn * 64 + (grp >> 1) * 8 + lr;  // + ntp*16
    const int b_col = (grp & 1) * 4;                  // + ks*8

    const int nk = K / GBK;
    float4 ra[4], rb[4];
#pragma unroll
    for (int i = 0; i < 4; i++) {
        ra[i] = *(const float4*)(Ag + (size_t)(32 * i) * K);
        rb[i] = *(const float4*)(Bg + (size_t)(32 * i) * K);
    }
    // store stage 0
#pragma unroll
    for (int i = 0; i < 4; i++) {
        uint4 va = make_uint4(f2tf(ra[i].x), f2tf(ra[i].y), f2tf(ra[i].z), f2tf(ra[i].w));
        uint4 vb = make_uint4(f2tf(rb[i].x), f2tf(rb[i].y), f2tf(rb[i].z), f2tf(rb[i].w));
        *(uint4*)&sA[(sr + 32 * i) * GLDS + sc] = va;
        *(uint4*)&sB[(sr + 32 * i) * GLDS + sc] = vb;
    }

    for (int kt = 0; kt < nk; ++kt) {
        __syncthreads();
        const int cur = kt & 1;
        if (kt + 1 < nk) {
            const float* Agn = Ag + (size_t)(kt + 1) * GBK;
            const float* Bgn = Bg + (size_t)(kt + 1) * GBK;
#pragma unroll
            for (int i = 0; i < 4; i++) {
                ra[i] = *(const float4*)(Agn + (size_t)(32 * i) * K);
                rb[i] = *(const float4*)(Bgn + (size_t)(32 * i) * K);
            }
        }
        float* cA = sA + cur * GSTAGE;
        float* cB = sB + cur * GSTAGE;
        const uint32_t aaddr = sptr(cA + a_row * GLDS + a_col);
        const uint32_t baddr = sptr(cB + b_row * GLDS + b_col);
#pragma unroll
        for (int ks = 0; ks < 4; ++ks) {
            uint32_t af[2][4];
            ldm_x4(af[0], aaddr + ks * 32);
            ldm_x4(af[1], aaddr + 16 * GLDS * 4 + ks * 32);
            uint32_t bf[4][4];
#pragma unroll
            for (int ntp = 0; ntp < 4; ++ntp)
                ldm_x4(bf[ntp], baddr + ntp * 16 * GLDS * 4 + ks * 32);
#pragma unroll
            for (int mt = 0; mt < 2; ++mt)
#pragma unroll
                for (int nt = 0; nt < 8; ++nt)
                    mma_tf32(acc[mt][nt], af[mt], &bf[nt >> 1][(nt & 1) * 2]);
        }
        if (kt + 1 < nk) {
            float* nA = sA + (cur ^ 1) * GSTAGE;
            float* nB = sB + (cur ^ 1) * GSTAGE;
#pragma unroll
            for (int i = 0; i < 4; i++) {
                uint4 va = make_uint4(f2tf(ra[i].x), f2tf(ra[i].y), f2tf(ra[i].z), f2tf(ra[i].w));
                uint4 vb = make_uint4(f2tf(rb[i].x), f2tf(rb[i].y), f2tf(rb[i].z), f2tf(rb[i].w));
                *(uint4*)&nA[(sr + 32 * i) * GLDS + sc] = va;
                *(uint4*)&nB[(sr + 32 * i) * GLDS + sc] = vb;
            }
        }
    }

    // epilogue
    const int row0 = m0 + wm * 32 + (lane >> 2);
    const int col0 = n0 + wn * 64 + (lane & 3) * 2;
#pragma unroll
    for (int mt = 0; mt < 2; ++mt)
#pragma unroll
        for (int nt = 0; nt < 8; ++nt) {
            int r = row0 + mt * 16;
            int c = col0 + nt * 8;
            float2* p0 = (float2*)&C[(size_t)r * N + c];
            float2* p1 = (float2*)&C[(size_t)(r + 8) * N + c];
            float2 v0 = make_float2(acc[mt][nt][0], acc[mt][nt][1]);
            float2 v1 = make_float2(acc[mt][nt][2], acc[mt][nt][3]);
            if (ADD) {
                float2 o0 = *p0, o1 = *p1;
                v0.x += o0.x; v0.y += o0.y; v1.x += o1.x; v1.y += o1.y;
            }
            *p0 = v0;
            *p1 = v1;
        }
}

// ---------------- flash attention (fp32, causal, GQA G=2) ----------------
constexpr int ATTN_SMEM = (2 * 128 * 65 + 64 * 65) * 4;  // 83200 bytes

__global__ __launch_bounds__(256) void attn_kernel(const float* __restrict__ Q,
                                                   const float* __restrict__ Kb,
                                                   const float* __restrict__ Vb,
                                                   float* __restrict__ O) {
    extern __shared__ float sm[];
    float* sQ = sm;
    float* sK = sm + 128 * 65;
    float* sP = sm + 2 * 128 * 65;
    const int h = blockIdx.y;
    const int qt0 = blockIdx.x * 64;
    const int kv = h >> 1;
    const float scale = 0.0883883476483184f;
    const int tid = threadIdx.x, tx = tid & 15, ty = tid >> 4;

    const float* qbase = Q + (size_t)qt0 * (Hn * HDn) + (size_t)h * HDn;
#pragma unroll
    for (int r = 0; r < 8; ++r) {
        int idx = tid + r * 256;
        int row = idx >> 5, c4 = idx & 31;
        float4 v = *(const float4*)(qbase + (size_t)row * (Hn * HDn) + c4 * 4);
        int dd = c4 * 4;
        sQ[(dd + 0) * 65 + row] = v.x * scale;
        sQ[(dd + 1) * 65 + row] = v.y * scale;
        sQ[(dd + 2) * 65 + row] = v.z * scale;
        sQ[(dd + 3) * 65 + row] = v.w * scale;
    }

    float m[4], l[4], o[4][8];
#pragma unroll
    for (int i = 0; i < 4; i++) {
        m[i] = -1e30f; l[i] = 0.f;
#pragma unroll
        for (int j = 0; j < 8; j++) o[i][j] = 0.f;
    }

    const float* Kh = Kb + (size_t)kv * Tn * HDn;
    const float* Vh = Vb + (size_t)kv * Tn * HDn;
    const int nkt = (qt0 >> 6) + 1;

    for (int kt = 0; kt < nkt; ++kt) {
        const int kt0 = kt << 6;
        __syncthreads();
#pragma unroll
        for (int r = 0; r < 8; ++r) {
            int idx = tid + r * 256;
            int row = idx >> 5, c4 = idx & 31;
            float4 v = *(const float4*)(Kh + (size_t)(kt0 + row) * HDn + c4 * 4);
            int dd = c4 * 4;
            sK[(dd + 0) * 65 + row] = v.x;
            sK[(dd + 1) * 65 + row] = v.y;
            sK[(dd + 2) * 65 + row] = v.z;
            sK[(dd + 3) * 65 + row] = v.w;
        }
        __syncthreads();

        float s[4][4] = {};
#pragma unroll 4
        for (int d = 0; d < 128; ++d) {
            float qa[4], ka[4];
#pragma unroll
            for (int i = 0; i < 4; i++) qa[i] = sQ[d * 65 + ty + 16 * i];
#pragma unroll
            for (int j = 0; j < 4; j++) ka[j] = sK[d * 65 + tx + 16 * j];
#pragma unroll
            for (int i = 0; i < 4; i++)
#pragma unroll
                for (int j = 0; j < 4; j++) s[i][j] = fmaf(qa[i], ka[j], s[i][j]);
        }
        if (kt == nkt - 1) {
#pragma unroll
            for (int i = 0; i < 4; i++)
#pragma unroll
                for (int j = 0; j < 4; j++)
                    if (kt0 + tx + 16 * j > qt0 + ty + 16 * i) s[i][j] = -1e30f;
        }
#pragma unroll
        for (int i = 0; i < 4; i++) {
            float rm = fmaxf(fmaxf(s[i][0], s[i][1]), fmaxf(s[i][2], s[i][3]));
#pragma unroll
            for (int off = 8; off; off >>= 1)
                rm = fmaxf(rm, __shfl_xor_sync(0xffffffffu, rm, off, 16));
            float mn = fmaxf(m[i], rm);
            float corr = expf(m[i] - mn);
            m[i] = mn;
            float su = 0.f;
#pragma unroll
            for (int j = 0; j < 4; j++) {
                s[i][j] = expf(s[i][j] - mn);
                su += s[i][j];
            }
#pragma unroll
            for (int off = 8; off; off >>= 1)
                su += __shfl_xor_sync(0xffffffffu, su, off, 16);
            l[i] = l[i] * corr + su;
#pragma unroll
            for (int j = 0; j < 8; j++) o[i][j] *= corr;
        }
#pragma unroll
        for (int i = 0; i < 4; i++)
#pragma unroll
            for (int j = 0; j < 4; j++)
                sP[(tx + 16 * j) * 65 + (ty + 16 * i)] = s[i][j];
        __syncthreads();

#pragma unroll
        for (int r = 0; r < 8; ++r) {
            int idx = tid + r * 256;
            int row = idx >> 5, c4 = idx & 31;
            ((float4*)sK)[row * 32 + c4] =
                *(const float4*)(Vh + (size_t)(kt0 + row) * HDn + c4 * 4);
        }
        __syncthreads();

#pragma unroll 4
        for (int kk = 0; kk < 64; ++kk) {
            float pv[4], vv[8];
#pragma unroll
            for (int i = 0; i < 4; i++) pv[i] = sP[kk * 65 + ty + 16 * i];
#pragma unroll
            for (int j = 0; j < 8; j++) vv[j] = sK[kk * 128 + tx + 16 * j];
#pragma unroll
            for (int i = 0; i < 4; i++)
#pragma unroll
                for (int j = 0; j < 8; j++) o[i][j] = fmaf(pv[i], vv[j], o[i][j]);
        }
    }

#pragma unroll
    for (int i = 0; i < 4; i++) {
        float inv = 1.0f / l[i];
        int trow = qt0 + ty + 16 * i;
#pragma unroll
        for (int j = 0; j < 8; j++)
            O[(size_t)trow * (Hn * HDn) + h * HDn + tx + 16 * j] = o[i][j] * inv;
    }
}

// ---------------- host orchestration ----------------
extern "C" void kernel_launch(void* const* d_in, const int* in_sizes, int n_in,
                              void* d_out, int out_size) {
    const float* emb = (const float*)d_in[0];
    const float* ln1 = (const float*)d_in[1];
    const float* qw  = (const float*)d_in[2];
    const float* kw  = (const float*)d_in[3];
    const float* vw  = (const float*)d_in[4];
    const float* qn  = (const float*)d_in[5];
    const float* kn  = (const float*)d_in[6];
    const float* ow  = (const float*)d_in[7];
    const float* ln2 = (const float*)d_in[8];
    const float* gw  = (const float*)d_in[9];
    const float* uw  = (const float*)d_in[10];
    const float* dw  = (const float*)d_in[11];
    const float* nw  = (const float*)d_in[12];

    float* out  = (float*)d_out;
    float* keys = out + (size_t)Tn * Dn;
    float* vals = keys + (size_t)Ln * KVn * Tn * HDn;

    float *ph, *px, *pq, *pao, *pkt, *pvt, *pg, *pu;
    cudaGetSymbolAddress((void**)&ph,  g_h);
    cudaGetSymbolAddress((void**)&px,  g_x);
    cudaGetSymbolAddress((void**)&pq,  g_q);
    cudaGetSymbolAddress((void**)&pao, g_ao);
    cudaGetSymbolAddress((void**)&pkt, g_kt);
    cudaGetSymbolAddress((void**)&pvt, g_vt);
    cudaGetSymbolAddress((void**)&pg,  g_gate);
    cudaGetSymbolAddress((void**)&pu,  g_up);

    cudaFuncSetAttribute(attn_kernel, cudaFuncAttributeMaxDynamicSharedMemorySize, ATTN_SMEM);
    cudaFuncSetAttribute(mma_nt_kernel<0>, cudaFuncAttributeMaxDynamicSharedMemorySize, GEMM_SMEM);
    cudaFuncSetAttribute(mma_nt_kernel<1>, cudaFuncAttributeMaxDynamicSharedMemorySize, GEMM_SMEM);

    cudaMemcpyAsync(ph, emb, sizeof(float) * Tn * Dn, cudaMemcpyDeviceToDevice);
    rope_tables_kernel<<<Tn, 64>>>();

    for (int i = 0; i < Ln; ++i) {
        rms_rows_kernel<<<Tn, 256>>>(ph, ln1 + (size_t)i * Dn, px);

        mma_nt_kernel<0><<<dim3((Hn * HDn) / GBN, Tn / GBM), 256, GEMM_SMEM>>>(
            px, qw + (size_t)i * (Hn * HDn) * Dn, pq, Tn, Hn * HDn, Dn);
        mma_nt_kernel<0><<<dim3((KVn * HDn) / GBN, Tn / GBM), 256, GEMM_SMEM>>>(
            px, kw + (size_t)i * (KVn * HDn) * Dn, pkt, Tn, KVn * HDn, Dn);
        mma_nt_kernel<0><<<dim3((KVn * HDn) / GBN, Tn / GBM), 256, GEMM_SMEM>>>(
            px, vw + (size_t)i * (KVn * HDn) * Dn, pvt, Tn, KVn * HDn, Dn);

        float* klayer = keys + (size_t)i * KVn * Tn * HDn;
        float* vlayer = vals + (size_t)i * KVn * Tn * HDn;

        qknorm_rope_kernel<<<dim3(Tn, Hn), 128>>>(pq, pq, qn + (size_t)i * HDn, Hn, 0);
        qknorm_rope_kernel<<<dim3(Tn, KVn), 128>>>(pkt, klayer, kn + (size_t)i * HDn, KVn, 1);
        v_transpose_kernel<<<(Tn * KVn * HDn) / 256, 256>>>(pvt, vlayer);

        attn_kernel<<<dim3(Tn / 64, Hn), 256, ATTN_SMEM>>>(pq, klayer, vlayer, pao);

        mma_nt_kernel<1><<<dim3(Dn / GBN, Tn / GBM), 256, GEMM_SMEM>>>(
            pao, ow + (size_t)i * Dn * (Hn * HDn), ph, Tn, Dn, Hn * HDn);

        rms_rows_kernel<<<Tn, 256>>>(ph, ln2 + (size_t)i * Dn, px);
        mma_nt_kernel<0><<<dim3(FFn / GBN, Tn / GBM), 256, GEMM_SMEM>>>(
            px, gw + (size_t)i * FFn * Dn, pg, Tn, FFn, Dn);
        mma_nt_kernel<0><<<dim3(FFn / GBN, Tn / GBM), 256, GEMM_SMEM>>>(
            px, uw + (size_t)i * FFn * Dn, pu, Tn, FFn, Dn);
        silu_mul_kernel<<<(Tn * FFn) / 256, 256>>>(pg, pu, Tn * FFn);
        mma_nt_kernel<1><<<dim3(Dn / GBN, Tn / GBM), 256, GEMM_SMEM>>>(
            pg, dw + (size_t)i * Dn * FFn, ph, Tn, Dn, FFn);
    }

    rms_rows_kernel<<<Tn, 256>>>(ph, nw, out);
}

// round 3
// speedup vs baseline: 4.5774x; 1.8627x over previous
#include <cuda_runtime.h>
#include <math.h>
#include <stdint.h>

// ---------------- problem constants ----------------
constexpr int Tn  = 2048;
constexpr int Dn  = 1024;
constexpr int Hn  = 16;
constexpr int KVn = 8;
constexpr int HDn = 128;
constexpr int FFn = 3072;
constexpr int Ln  = 5;
constexpr float EPSf = 1e-6f;

// ---------------- scratch ----------------
__device__ float g_h [Tn * Dn];
__device__ float g_x [Tn * Dn];
__device__ float g_q [Tn * Hn * HDn];
__device__ float g_ao[Tn * Hn * HDn];
__device__ float g_kt[Tn * KVn * HDn];
__device__ float g_vt[Tn * KVn * HDn];
__device__ float g_gate[Tn * FFn];
__device__ float g_up  [Tn * FFn];
__device__ float g_cos[Tn * 64];
__device__ float g_sin[Tn * 64];

// ---------------- PTX helpers ----------------
__device__ __forceinline__ uint32_t sptr(const void* p) {
    return (uint32_t)__cvta_generic_to_shared(p);
}
__device__ __forceinline__ uint32_t f2tf(float f) {
    uint32_t u;
    asm("cvt.rna.tf32.f32 %0, %1;" : "=r"(u) : "f"(f));
    return u;
}
__device__ __forceinline__ void ldm_x4(uint32_t* r, uint32_t addr) {
    asm volatile("ldmatrix.sync.aligned.m8n8.x4.shared.b16 {%0,%1,%2,%3}, [%4];"
                 : "=r"(r[0]), "=r"(r[1]), "=r"(r[2]), "=r"(r[3]) : "r"(addr));
}
__device__ __forceinline__ void mma_tf32(float* c, const uint32_t* a, const uint32_t* b) {
    asm volatile("mma.sync.aligned.m16n8k8.row.col.f32.tf32.tf32.f32 "
                 "{%0,%1,%2,%3}, {%4,%5,%6,%7}, {%8,%9}, {%0,%1,%2,%3};"
                 : "+f"(c[0]), "+f"(c[1]), "+f"(c[2]), "+f"(c[3])
                 : "r"(a[0]), "r"(a[1]), "r"(a[2]), "r"(a[3]), "r"(b[0]), "r"(b[1]));
}

// ---------------- RoPE tables ----------------
__global__ void rope_tables_kernel() {
    int t = blockIdx.x;
    int j = threadIdx.x;
    float inv = 1.0f / powf(1.0e6f, (float)j * (1.0f / 64.0f));
    float ang = (float)t * inv;
    g_cos[t * 64 + j] = cosf(ang);
    g_sin[t * 64 + j] = sinf(ang);
}

// ---------------- RMSNorm rows ----------------
__global__ void rms_rows_kernel(const float* __restrict__ in,
                                const float* __restrict__ w,
                                float* __restrict__ out) {
    int t = blockIdx.x;
    const float4* ip = (const float4*)(in + (size_t)t * Dn);
    const float4* wp = (const float4*)w;
    float4 v = ip[threadIdx.x];
    float s = v.x * v.x + v.y * v.y + v.z * v.z + v.w * v.w;
#pragma unroll
    for (int off = 16; off; off >>= 1) s += __shfl_xor_sync(0xffffffffu, s, off);
    __shared__ float ws[8];
    if ((threadIdx.x & 31) == 0) ws[threadIdx.x >> 5] = s;
    __syncthreads();
    float tot = 0.f;
#pragma unroll
    for (int i = 0; i < 8; i++) tot += ws[i];
    float r = rsqrtf(tot * (1.0f / (float)Dn) + EPSf);
    float4 wv = wp[threadIdx.x];
    float4 o = make_float4(v.x * r * wv.x, v.y * r * wv.y, v.z * r * wv.z, v.w * r * wv.w);
    ((float4*)(out + (size_t)t * Dn))[threadIdx.x] = o;
}

// ---------------- per-head RMSNorm + RoPE ----------------
__global__ void qknorm_rope_kernel(const float* __restrict__ in,
                                   float* __restrict__ out,
                                   const float* __restrict__ w,
                                   int NH, int transposed) {
    int t = blockIdx.x, h = blockIdx.y, d = threadIdx.x;
    const float* row = in + ((size_t)t * NH + h) * HDn;
    float v = row[d];
    float s = v * v;
#pragma unroll
    for (int off = 16; off; off >>= 1) s += __shfl_xor_sync(0xffffffffu, s, off);
    __shared__ float ws[4];
    if ((d & 31) == 0) ws[d >> 5] = s;
    __syncthreads();
    float tot = ws[0] + ws[1] + ws[2] + ws[3];
    float r = rsqrtf(tot * (1.0f / (float)HDn) + EPSf);
    float xn = v * r * w[d];
    __shared__ float sh[128];
    sh[d] = xn;
    __syncthreads();
    float other = (d < 64) ? -sh[d + 64] : sh[d - 64];
    int j = d & 63;
    float c = g_cos[t * 64 + j];
    float sn = g_sin[t * 64 + j];
    float o = xn * c + other * sn;
    size_t oidx = transposed ? (((size_t)h * Tn + t) * HDn + d)
                             : (((size_t)t * NH + h) * HDn + d);
    out[oidx] = o;
}

// ---------------- V transpose ----------------
__global__ void v_transpose_kernel(const float* __restrict__ in, float* __restrict__ out) {
    int idx = blockIdx.x * blockDim.x + threadIdx.x;
    int kv  = idx / (Tn * HDn);
    int rem = idx - kv * (Tn * HDn);
    int t   = rem / HDn;
    int d   = rem - t * HDn;
    out[idx] = in[((size_t)t * KVn + kv) * HDn + d];
}

// ---------------- silu(g)*u ----------------
__global__ void silu_mul_kernel(float* __restrict__ g, const float* __restrict__ u, int n) {
    int idx = blockIdx.x * blockDim.x + threadIdx.x;
    if (idx < n) {
        float gv = g[idx];
        float sv = gv / (1.0f + expf(-gv));
        g[idx] = sv * u[idx];
    }
}

// ---------------- TF32 tensor-core GEMM NT body ----------------
constexpr int GBM = 128, GBN = 128, GBK = 32, GPAD = 4, GLDS = GBK + GPAD;
constexpr int GSTAGE = GBM * GLDS;
constexpr int GEMM_SMEM = 4 * GSTAGE * 4;

template <int ADD>
__device__ __forceinline__ void gemm_body(const float* __restrict__ A,
                                          const float* __restrict__ B,
                                          float* __restrict__ C,
                                          int N, int K, int m0, int n0,
                                          float* smem) {
    float* sA = smem;
    float* sB = smem + 2 * GSTAGE;

    const int tid = threadIdx.x, lane = tid & 31, wid = tid >> 5;
    const int wm = wid & 3, wn = wid >> 2;

    const int sr = tid >> 3;
    const int sc = (tid & 7) * 4;
    const float* Ag = A + (size_t)(m0 + sr) * K + sc;
    const float* Bg = B + (size_t)(n0 + sr) * K + sc;

    float acc[2][8][4];
#pragma unroll
    for (int i = 0; i < 2; i++)
#pragma unroll
        for (int j = 0; j < 8; j++)
#pragma unroll
            for (int q = 0; q < 4; q++) acc[i][j][q] = 0.f;

    const int grp = lane >> 3, lr = lane & 7;
    const int a_row = wm * 32 + (grp & 1) * 8 + lr;
    const int a_col = (grp >> 1) * 4;
    const int b_row = wn * 64 + (grp >> 1) * 8 + lr;
    const int b_col = (grp & 1) * 4;

    const int nk = K / GBK;
    float4 ra[4], rb[4];
#pragma unroll
    for (int i = 0; i < 4; i++) {
        ra[i] = *(const float4*)(Ag + (size_t)(32 * i) * K);
        rb[i] = *(const float4*)(Bg + (size_t)(32 * i) * K);
    }
#pragma unroll
    for (int i = 0; i < 4; i++) {
        uint4 va = make_uint4(f2tf(ra[i].x), f2tf(ra[i].y), f2tf(ra[i].z), f2tf(ra[i].w));
        uint4 vb = make_uint4(f2tf(rb[i].x), f2tf(rb[i].y), f2tf(rb[i].z), f2tf(rb[i].w));
        *(uint4*)&sA[(sr + 32 * i) * GLDS + sc] = va;
        *(uint4*)&sB[(sr + 32 * i) * GLDS + sc] = vb;
    }

    for (int kt = 0; kt < nk; ++kt) {
        __syncthreads();
        const int cur = kt & 1;
        if (kt + 1 < nk) {
            const float* Agn = Ag + (size_t)(kt + 1) * GBK;
            const float* Bgn = Bg + (size_t)(kt + 1) * GBK;
#pragma unroll
            for (int i = 0; i < 4; i++) {
                ra[i] = *(const float4*)(Agn + (size_t)(32 * i) * K);
                rb[i] = *(const float4*)(Bgn + (size_t)(32 * i) * K);
            }
        }
        float* cA = sA + cur * GSTAGE;
        float* cB = sB + cur * GSTAGE;
        const uint32_t aaddr = sptr(cA + a_row * GLDS + a_col);
        const uint32_t baddr = sptr(cB + b_row * GLDS + b_col);
#pragma unroll
        for (int ks = 0; ks < 4; ++ks) {
            uint32_t af[2][4];
            ldm_x4(af[0], aaddr + ks * 32);
            ldm_x4(af[1], aaddr + 16 * GLDS * 4 + ks * 32);
            uint32_t bf[4][4];
#pragma unroll
            for (int ntp = 0; ntp < 4; ++ntp)
                ldm_x4(bf[ntp], baddr + ntp * 16 * GLDS * 4 + ks * 32);
#pragma unroll
            for (int mt = 0; mt < 2; ++mt)
#pragma unroll
                for (int nt = 0; nt < 8; ++nt)
                    mma_tf32(acc[mt][nt], af[mt], &bf[nt >> 1][(nt & 1) * 2]);
        }
        if (kt + 1 < nk) {
            float* nA = sA + (cur ^ 1) * GSTAGE;
            float* nB = sB + (cur ^ 1) * GSTAGE;
#pragma unroll
            for (int i = 0; i < 4; i++) {
                uint4 va = make_uint4(f2tf(ra[i].x), f2tf(ra[i].y), f2tf(ra[i].z), f2tf(ra[i].w));
                uint4 vb = make_uint4(f2tf(rb[i].x), f2tf(rb[i].y), f2tf(rb[i].z), f2tf(rb[i].w));
                *(uint4*)&nA[(sr + 32 * i) * GLDS + sc] = va;
                *(uint4*)&nB[(sr + 32 * i) * GLDS + sc] = vb;
            }
        }
    }

    const int row0 = m0 + wm * 32 + (lane >> 2);
    const int col0 = n0 + wn * 64 + (lane & 3) * 2;
#pragma unroll
    for (int mt = 0; mt < 2; ++mt)
#pragma unroll
        for (int nt = 0; nt < 8; ++nt) {
            int r = row0 + mt * 16;
            int c = col0 + nt * 8;
            float2* p0 = (float2*)&C[(size_t)r * N + c];
            float2* p1 = (float2*)&C[(size_t)(r + 8) * N + c];
            float2 v0 = make_float2(acc[mt][nt][0], acc[mt][nt][1]);
            float2 v1 = make_float2(acc[mt][nt][2], acc[mt][nt][3]);
            if (ADD) {
                float2 o0 = *p0, o1 = *p1;
                v0.x += o0.x; v0.y += o0.y; v1.x += o1.x; v1.y += o1.y;
            }
            *p0 = v0;
            *p1 = v1;
        }
}

template <int ADD>
__global__ __launch_bounds__(256) void mma_nt_kernel(const float* __restrict__ A,
                                                     const float* __restrict__ B,
                                                     float* __restrict__ C,
                                                     int N, int K) {
    extern __shared__ float smem[];
    gemm_body<ADD>(A, B, C, N, K, blockIdx.y * GBM, blockIdx.x * GBN, smem);
}

// fused QKV: grid.x = 16 (q) + 8 (k) + 8 (v)
__global__ __launch_bounds__(256) void mma_qkv_kernel(const float* __restrict__ A,
                                                      const float* __restrict__ qw,
                                                      const float* __restrict__ kw,
                                                      const float* __restrict__ vw,
                                                      float* __restrict__ q,
                                                      float* __restrict__ k,
                                                      float* __restrict__ v) {
    extern __shared__ float smem[];
    int bx = blockIdx.x;
    const float* B; float* C; int N, n0;
    if (bx < 16)      { B = qw; C = q; N = Hn * HDn;  n0 = bx * GBN; }
    else if (bx < 24) { B = kw; C = k; N = KVn * HDn; n0 = (bx - 16) * GBN; }
    else              { B = vw; C = v; N = KVn * HDn; n0 = (bx - 24) * GBN; }
    gemm_body<0>(A, B, C, N, Dn, blockIdx.y * GBM, n0, smem);
}

// fused gate+up: grid.x = 24 + 24
__global__ __launch_bounds__(256) void mma_gu_kernel(const float* __restrict__ A,
                                                     const float* __restrict__ gw,
                                                     const float* __restrict__ uw,
                                                     float* __restrict__ g,
                                                     float* __restrict__ u) {
    extern __shared__ float smem[];
    int bx = blockIdx.x;
    const float* B; float* C; int n0;
    if (bx < 24) { B = gw; C = g; n0 = bx * GBN; }
    else         { B = uw; C = u; n0 = (bx - 24) * GBN; }
    gemm_body<0>(A, B, C, FFn, Dn, blockIdx.y * GBM, n0, smem);
}

// ---------------- TF32 MMA flash attention ----------------
// 128 threads (4 warps); per CTA: 64 q rows of one head. K-tile = 64.
constexpr int A_KS = 132;   // sK row stride (floats)
constexpr int A_VS = 68;    // sV row stride
constexpr int A_PS = 68;    // sP row stride
constexpr int ATTN_SMEM = (64 * A_KS + 128 * A_VS + 64 * A_PS) * 4;  // 86016

__global__ __launch_bounds__(128) void attn_mma_kernel(const float* __restrict__ Q,
                                                       const float* __restrict__ Kb,
                                                       const float* __restrict__ Vb,
                                                       float* __restrict__ O) {
    extern __shared__ float sm[];
    float* sK = sm;                     // [64][132]: Q staging, then K tiles
    float* sV = sm + 64 * A_KS;         // [128][68]: V transposed (d-major)
    float* sP = sV + 128 * A_VS;        // [64][68]:  P (per-warp 16-row slices)

    const int h = blockIdx.y;
    const int qt0 = blockIdx.x * 64;
    const int kv = h >> 1;
    const float scale = 0.0883883476483184f;  // 1/sqrt(128)
    const int tid = threadIdx.x, lane = tid & 31, wid = tid >> 5;
    const int grp = lane >> 3, lr = lane & 7;
    const int r0 = lane >> 2, c0 = (lane & 3) * 2;

    // ---- stage Q (scaled, tf32) into sK, extract per-warp fragments ----
    const float* qbase = Q + (size_t)qt0 * (Hn * HDn) + (size_t)h * HDn;
#pragma unroll
    for (int r = 0; r < 16; ++r) {
        int idx = tid + r * 128;
        int row = idx >> 5, c4 = idx & 31;
        float4 v = *(const float4*)(qbase + (size_t)row * (Hn * HDn) + c4 * 4);
        uint4 u = make_uint4(f2tf(v.x * scale), f2tf(v.y * scale),
                             f2tf(v.z * scale), f2tf(v.w * scale));
        *(uint4*)&sK[row * A_KS + c4 * 4] = u;
    }
    __syncthreads();
    uint32_t qf[16][4];
    {
        uint32_t qaddr = sptr(sK + (wid * 16 + (grp & 1) * 8 + lr) * A_KS + (grp >> 1) * 4);
#pragma unroll
        for (int ks = 0; ks < 16; ++ks) ldm_x4(qf[ks], qaddr + ks * 32);
    }
    __syncthreads();

    float o[16][4];
#pragma unroll
    for (int i = 0; i < 16; i++)
#pragma unroll
        for (int j = 0; j < 4; j++) o[i][j] = 0.f;
    float mreg[2] = {-1e30f, -1e30f}, lreg[2] = {0.f, 0.f};

    const float* Kh = Kb + (size_t)kv * Tn * HDn;
    const float* Vh = Vb + (size_t)kv * Tn * HDn;
    const int nkt = (qt0 >> 6) + 1;

    float* myP = sP + wid * 16 * A_PS;
    const uint32_t kaddr = sptr(sK + ((grp >> 1) * 8 + lr) * A_KS + (grp & 1) * 4);
    const uint32_t paddr = sptr(myP + ((grp & 1) * 8 + lr) * A_PS + (grp >> 1) * 4);
    const uint32_t vaddr = sptr(sV + ((grp >> 1) * 8 + lr) * A_VS + (grp & 1) * 4);

    for (int kt = 0; kt < nkt; ++kt) {
        const int kt0 = kt << 6;
        if (kt) __syncthreads();
        // stage K natural [kpos][d] (B operand for S)
#pragma unroll
        for (int r = 0; r < 16; ++r) {
            int idx = tid + r * 128;
            int row = idx >> 5, c4 = idx & 31;
            float4 v = *(const float4*)(Kh + (size_t)(kt0 + row) * HDn + c4 * 4);
            uint4 u = make_uint4(f2tf(v.x), f2tf(v.y), f2tf(v.z), f2tf(v.w));
            *(uint4*)&sK[row * A_KS + c4 * 4] = u;
        }
        // stage V transposed [d][kpos], conflict-free 128-bit stores (d-major lanes)
        {
            const int d = tid;  // 0..127
#pragma unroll
            for (int rg = 0; rg < 16; ++rg) {
                float v0 = Vh[(size_t)(kt0 + rg * 4 + 0) * HDn + d];
                float v1 = Vh[(size_t)(kt0 + rg * 4 + 1) * HDn + d];
                float v2 = Vh[(size_t)(kt0 + rg * 4 + 2) * HDn + d];
                float v3 = Vh[(size_t)(kt0 + rg * 4 + 3) * HDn + d];
                uint4 u = make_uint4(f2tf(v0), f2tf(v1), f2tf(v2), f2tf(v3));
                *(uint4*)&sV[d * A_VS + rg * 4] = u;
            }
        }
        __syncthreads();

        // ---- S = Q @ K^T (64x64 per CTA, m16 per warp) ----
        float s[8][4];
#pragma unroll
        for (int i = 0; i < 8; i++)
#pragma unroll
            for (int j = 0; j < 4; j++) s[i][j] = 0.f;
#pragma unroll
        for (int ks = 0; ks < 16; ++ks) {
            uint32_t bf[4][4];
#pragma unroll
            for (int ntp = 0; ntp < 4; ++ntp)
                ldm_x4(bf[ntp], kaddr + (ntp * 16 * A_KS) * 4 + ks * 32);
#pragma unroll
            for (int nt = 0; nt < 8; ++nt)
                mma_tf32(s[nt], qf[ks], &bf[nt >> 1][(nt & 1) * 2]);
        }

        // causal mask (diagonal tile only)
        if (kt == nkt - 1) {
            int row0g = qt0 + wid * 16 + r0;
#pragma unroll
            for (int nt = 0; nt < 8; ++nt) {
                int colg = kt0 + nt * 8 + c0;
                if (colg > row0g)          s[nt][0] = -1e30f;
                if (colg + 1 > row0g)      s[nt][1] = -1e30f;
                if (colg > row0g + 8)      s[nt][2] = -1e30f;
                if (colg + 1 > row0g + 8)  s[nt][3] = -1e30f;
            }
        }

        // ---- online softmax (2 rows per thread; 4-lane row groups) ----
#pragma unroll
        for (int hf = 0; hf < 2; ++hf) {
            float rm = -1e30f;
#pragma unroll
            for (int nt = 0; nt < 8; ++nt)
                rm = fmaxf(rm, fmaxf(s[nt][2 * hf], s[nt][2 * hf + 1]));
            rm = fmaxf(rm, __shfl_xor_sync(0xffffffffu, rm, 1));
            rm = fmaxf(rm, __shfl_xor_sync(0xffffffffu, rm, 2));
            float mn = fmaxf(mreg[hf], rm);
            float corr = __expf(mreg[hf] - mn);
            mreg[hf] = mn;
            float su = 0.f;
#pragma unroll
            for (int nt = 0; nt < 8; ++nt) {
                float e0 = __expf(s[nt][2 * hf] - mn);
                float e1 = __expf(s[nt][2 * hf + 1] - mn);
                s[nt][2 * hf] = e0;
                s[nt][2 * hf + 1] = e1;
                su += e0 + e1;
            }
            su += __shfl_xor_sync(0xffffffffu, su, 1);
            su += __shfl_xor_sync(0xffffffffu, su, 2);
            lreg[hf] = lreg[hf] * corr + su;
#pragma unroll
            for (int nt = 0; nt < 16; ++nt) {
                o[nt][2 * hf] *= corr;
                o[nt][2 * hf + 1] *= corr;
            }
        }

        // ---- P to warp-private smem (tf32), no cross-warp sync needed ----
#pragma unroll
        for (int nt = 0; nt < 8; ++nt) {
            *(uint2*)&myP[r0 * A_PS + nt * 8 + c0] =
                make_uint2(f2tf(s[nt][0]), f2tf(s[nt][1]));
            *(uint2*)&myP[(r0 + 8) * A_PS + nt * 8 + c0] =
                make_uint2(f2tf(s[nt][2]), f2tf(s[nt][3]));
        }
        __syncwarp();

        // ---- O += P @ V ----
#pragma unroll
        for (int ks = 0; ks < 8; ++ks) {
            uint32_t pf[4];
            ldm_x4(pf, paddr + ks * 32);
#pragma unroll
            for (int np = 0; np < 8; ++np) {
                uint32_t bf[4];
                ldm_x4(bf, vaddr + (np * 16 * A_VS) * 4 + ks * 32);
                mma_tf32(o[2 * np],     pf, &bf[0]);
                mma_tf32(o[2 * np + 1], pf, &bf[2]);
            }
        }
    }

    // ---- epilogue ----
    float inv0 = 1.0f / lreg[0], inv1 = 1.0f / lreg[1];
    int row0g = qt0 + wid * 16 + r0;
#pragma unroll
    for (int nt = 0; nt < 16; ++nt) {
        size_t base = (size_t)h * HDn + nt * 8 + c0;
        *(float2*)&O[(size_t)row0g * (Hn * HDn) + base] =
            make_float2(o[nt][0] * inv0, o[nt][1] * inv0);
        *(float2*)&O[(size_t)(row0g + 8) * (Hn * HDn) + base] =
            make_float2(o[nt][2] * inv1, o[nt][3] * inv1);
    }
}

// ---------------- host orchestration ----------------
extern "C" void kernel_launch(void* const* d_in, const int* in_sizes, int n_in,
                              void* d_out, int out_size) {
    const float* emb = (const float*)d_in[0];
    const float* ln1 = (const float*)d_in[1];
    const float* qw  = (const float*)d_in[2];
    const float* kw  = (const float*)d_in[3];
    const float* vw  = (const float*)d_in[4];
    const float* qn  = (const float*)d_in[5];
    const float* kn  = (const float*)d_in[6];
    const float* ow  = (const float*)d_in[7];
    const float* ln2 = (const float*)d_in[8];
    const float* gw  = (const float*)d_in[9];
    const float* uw  = (const float*)d_in[10];
    const float* dw  = (const float*)d_in[11];
    const float* nw  = (const float*)d_in[12];

    float* out  = (float*)d_out;
    float* keys = out + (size_t)Tn * Dn;
    float* vals = keys + (size_t)Ln * KVn * Tn * HDn;

    float *ph, *px, *pq, *pao, *pkt, *pvt, *pg, *pu;
    cudaGetSymbolAddress((void**)&ph,  g_h);
    cudaGetSymbolAddress((void**)&px,  g_x);
    cudaGetSymbolAddress((void**)&pq,  g_q);
    cudaGetSymbolAddress((void**)&pao, g_ao);
    cudaGetSymbolAddress((void**)&pkt, g_kt);
    cudaGetSymbolAddress((void**)&pvt, g_vt);
    cudaGetSymbolAddress((void**)&pg,  g_gate);
    cudaGetSymbolAddress((void**)&pu,  g_up);

    cudaFuncSetAttribute(attn_mma_kernel, cudaFuncAttributeMaxDynamicSharedMemorySize, ATTN_SMEM);
    cudaFuncSetAttribute(mma_nt_kernel<0>, cudaFuncAttributeMaxDynamicSharedMemorySize, GEMM_SMEM);
    cudaFuncSetAttribute(mma_nt_kernel<1>, cudaFuncAttributeMaxDynamicSharedMemorySize, GEMM_SMEM);
    cudaFuncSetAttribute(mma_qkv_kernel, cudaFuncAttributeMaxDynamicSharedMemorySize, GEMM_SMEM);
    cudaFuncSetAttribute(mma_gu_kernel, cudaFuncAttributeMaxDynamicSharedMemorySize, GEMM_SMEM);

    cudaMemcpyAsync(ph, emb, sizeof(float) * Tn * Dn, cudaMemcpyDeviceToDevice);
    rope_tables_kernel<<<Tn, 64>>>();

    for (int i = 0; i < Ln; ++i) {
        rms_rows_kernel<<<Tn, 256>>>(ph, ln1 + (size_t)i * Dn, px);

        mma_qkv_kernel<<<dim3(32, Tn / GBM), 256, GEMM_SMEM>>>(
            px, qw + (size_t)i * (Hn * HDn) * Dn, kw + (size_t)i * (KVn * HDn) * Dn,
            vw + (size_t)i * (KVn * HDn) * Dn, pq, pkt, pvt);

        float* klayer = keys + (size_t)i * KVn * Tn * HDn;
        float* vlayer = vals + (size_t)i * KVn * Tn * HDn;

        qknorm_rope_kernel<<<dim3(Tn, Hn), 128>>>(pq, pq, qn + (size_t)i * HDn, Hn, 0);
        qknorm_rope_kernel<<<dim3(Tn, KVn), 128>>>(pkt, klayer, kn + (size_t)i * HDn, KVn, 1);
        v_transpose_kernel<<<(Tn * KVn * HDn) / 256, 256>>>(pvt, vlayer);

        attn_mma_kernel<<<dim3(Tn / 64, Hn), 128, ATTN_SMEM>>>(pq, klayer, vlayer, pao);

        mma_nt_kernel<1><<<dim3(Dn / GBN, Tn / GBM), 256, GEMM_SMEM>>>(
            pao, ow + (size_t)i * Dn * (Hn * HDn), ph, Dn, Hn * HDn);

        rms_rows_kernel<<<Tn, 256>>>(ph, ln2 + (size_t)i * Dn, px);
        mma_gu_kernel<<<dim3(48, Tn / GBM), 256, GEMM_SMEM>>>(
            px, gw + (size_t)i * FFn * Dn, uw + (size_t)i * FFn * Dn, pg, pu);
        silu_mul_kernel<<<(Tn * FFn) / 256, 256>>>(pg, pu, Tn * FFn);
        mma_nt_kernel<1><<<dim3(Dn / GBN, Tn / GBM), 256, GEMM_SMEM>>>(
            pg, dw + (size_t)i * Dn * FFn, ph, Dn, FFn);
    }

    rms_rows_kernel<<<Tn, 256>>>(ph, nw, out);
}

// round 4
// speedup vs baseline: 4.6234x; 1.0101x over previous
#include <cuda_runtime.h>
#include <math.h>
#include <stdint.h>

// ---------------- problem constants ----------------
constexpr int Tn  = 2048;
constexpr int Dn  = 1024;
constexpr int Hn  = 16;
constexpr int KVn = 8;
constexpr int HDn = 128;
constexpr int FFn = 3072;
constexpr int Ln  = 5;
constexpr float EPSf = 1e-6f;

// ---------------- scratch ----------------
__device__ float g_h [Tn * Dn];
__device__ float g_x [Tn * Dn];
__device__ float g_q [Tn * Hn * HDn];
__device__ float g_ao[Tn * Hn * HDn];
__device__ float g_kt[Tn * KVn * HDn];
__device__ float g_vt[Tn * KVn * HDn];
__device__ float g_gate[Tn * FFn];
__device__ float g_up  [Tn * FFn];
__device__ float g_cos[Tn * 64];
__device__ float g_sin[Tn * 64];

// tf32-rounded weight copies (one big arena)
constexpr size_t W_Q  = 0;
constexpr size_t W_K  = W_Q + (size_t)Ln * Hn * HDn * Dn;    // q: 5*2048*1024
constexpr size_t W_V  = W_K + (size_t)Ln * KVn * HDn * Dn;
constexpr size_t W_O  = W_V + (size_t)Ln * KVn * HDn * Dn;
constexpr size_t W_G  = W_O + (size_t)Ln * Dn * Hn * HDn;
constexpr size_t W_U  = W_G + (size_t)Ln * FFn * Dn;
constexpr size_t W_D  = W_U + (size_t)Ln * FFn * Dn;
constexpr size_t W_TOT= W_D + (size_t)Ln * Dn * FFn;
__device__ float g_wc[W_TOT];

// ---------------- PTX helpers ----------------
__device__ __forceinline__ uint32_t sptr(const void* p) {
    return (uint32_t)__cvta_generic_to_shared(p);
}
__device__ __forceinline__ uint32_t f2tf(float f) {
    uint32_t u;
    asm("cvt.rna.tf32.f32 %0, %1;" : "=r"(u) : "f"(f));
    return u;
}
__device__ __forceinline__ float f2tff(float f) {
    return __uint_as_float(f2tf(f));
}
__device__ __forceinline__ void ldm_x4(uint32_t* r, uint32_t addr) {
    asm volatile("ldmatrix.sync.aligned.m8n8.x4.shared.b16 {%0,%1,%2,%3}, [%4];"
                 : "=r"(r[0]), "=r"(r[1]), "=r"(r[2]), "=r"(r[3]) : "r"(addr));
}
__device__ __forceinline__ void mma_tf32(float* c, const uint32_t* a, const uint32_t* b) {
    asm volatile("mma.sync.aligned.m16n8k8.row.col.f32.tf32.tf32.f32 "
                 "{%0,%1,%2,%3}, {%4,%5,%6,%7}, {%8,%9}, {%0,%1,%2,%3};"
                 : "+f"(c[0]), "+f"(c[1]), "+f"(c[2]), "+f"(c[3])
                 : "r"(a[0]), "r"(a[1]), "r"(a[2]), "r"(a[3]), "r"(b[0]), "r"(b[1]));
}
__device__ __forceinline__ void cp_async16(uint32_t dst, const void* src) {
    asm volatile("cp.async.ca.shared.global [%0], [%1], 16;" :: "r"(dst), "l"(src));
}
__device__ __forceinline__ void cp_commit() {
    asm volatile("cp.async.commit_group;" ::: "memory");
}
template <int N>
__device__ __forceinline__ void cp_wait() {
    asm volatile("cp.async.wait_group %0;" :: "n"(N) : "memory");
}

// ---------------- weight tf32 pre-round ----------------
__global__ void conv_tf32_kernel(const float4* __restrict__ in, float4* __restrict__ out, int n4) {
    int i = blockIdx.x * blockDim.x + threadIdx.x;
    if (i < n4) {
        float4 v = in[i];
        out[i] = make_float4(f2tff(v.x), f2tff(v.y), f2tff(v.z), f2tff(v.w));
    }
}

// ---------------- RoPE tables ----------------
__global__ void rope_tables_kernel() {
    int t = blockIdx.x;
    int j = threadIdx.x;
    float inv = 1.0f / powf(1.0e6f, (float)j * (1.0f / 64.0f));
    float ang = (float)t * inv;
    g_cos[t * 64 + j] = cosf(ang);
    g_sin[t * 64 + j] = sinf(ang);
}

// ---------------- RMSNorm rows (ROUND: emit tf32-rounded) ----------------
template <int ROUND>
__global__ void rms_rows_kernel(const float* __restrict__ in,
                                const float* __restrict__ w,
                                float* __restrict__ out) {
    int t = blockIdx.x;
    const float4* ip = (const float4*)(in + (size_t)t * Dn);
    const float4* wp = (const float4*)w;
    float4 v = ip[threadIdx.x];
    float s = v.x * v.x + v.y * v.y + v.z * v.z + v.w * v.w;
#pragma unroll
    for (int off = 16; off; off >>= 1) s += __shfl_xor_sync(0xffffffffu, s, off);
    __shared__ float ws[8];
    if ((threadIdx.x & 31) == 0) ws[threadIdx.x >> 5] = s;
    __syncthreads();
    float tot = 0.f;
#pragma unroll
    for (int i = 0; i < 8; i++) tot += ws[i];
    float r = rsqrtf(tot * (1.0f / (float)Dn) + EPSf);
    float4 wv = wp[threadIdx.x];
    float4 o = make_float4(v.x * r * wv.x, v.y * r * wv.y, v.z * r * wv.z, v.w * r * wv.w);
    if (ROUND) o = make_float4(f2tff(o.x), f2tff(o.y), f2tff(o.z), f2tff(o.w));
    ((float4*)(out + (size_t)t * Dn))[threadIdx.x] = o;
}

// ---------------- per-head RMSNorm + RoPE ----------------
__global__ void qknorm_rope_kernel(const float* __restrict__ in,
                                   float* __restrict__ out,
                                   const float* __restrict__ w,
                                   int NH, int transposed) {
    int t = blockIdx.x, h = blockIdx.y, d = threadIdx.x;
    const float* row = in + ((size_t)t * NH + h) * HDn;
    float v = row[d];
    float s = v * v;
#pragma unroll
    for (int off = 16; off; off >>= 1) s += __shfl_xor_sync(0xffffffffu, s, off);
    __shared__ float ws[4];
    if ((d & 31) == 0) ws[d >> 5] = s;
    __syncthreads();
    float tot = ws[0] + ws[1] + ws[2] + ws[3];
    float r = rsqrtf(tot * (1.0f / (float)HDn) + EPSf);
    float xn = v * r * w[d];
    __shared__ float sh[128];
    sh[d] = xn;
    __syncthreads();
    float other = (d < 64) ? -sh[d + 64] : sh[d - 64];
    int j = d & 63;
    float c = g_cos[t * 64 + j];
    float sn = g_sin[t * 64 + j];
    float o = xn * c + other * sn;
    size_t oidx = transposed ? (((size_t)h * Tn + t) * HDn + d)
                             : (((size_t)t * NH + h) * HDn + d);
    out[oidx] = o;
}

// ---------------- V transpose (float4) ----------------
__global__ void v_transpose_kernel(const float4* __restrict__ in, float4* __restrict__ out) {
    int idx = blockIdx.x * blockDim.x + threadIdx.x;   // over output float4s
    int kv  = idx / (Tn * 32);
    int rem = idx - kv * (Tn * 32);
    int t   = rem >> 5;
    int d4  = rem & 31;
    out[idx] = in[((size_t)t * KVn + kv) * 32 + d4];
}

// ---------------- silu(g)*u (emit tf32) ----------------
__global__ void silu_mul_kernel(float4* __restrict__ g, const float4* __restrict__ u, int n4) {
    int idx = blockIdx.x * blockDim.x + threadIdx.x;
    if (idx < n4) {
        float4 gv = g[idx], uv = u[idx];
        gv.x = f2tff(gv.x / (1.0f + __expf(-gv.x)) * uv.x);
        gv.y = f2tff(gv.y / (1.0f + __expf(-gv.y)) * uv.y);
        gv.z = f2tff(gv.z / (1.0f + __expf(-gv.z)) * uv.z);
        gv.w = f2tff(gv.w / (1.0f + __expf(-gv.w)) * uv.w);
        g[idx] = gv;
    }
}

// ---------------- TF32 tensor-core GEMM NT (cp.async 3-stage) ----------------
// Inputs must already be tf32-rounded in gmem.
constexpr int GBM = 128, GBN = 128, GBK = 32, GPAD = 4, GLDS = GBK + GPAD;  // 36
constexpr int GSTAGE  = GBM * GLDS;          // floats per operand-stage
constexpr int GSTAGEB = GSTAGE * 4;          // bytes
constexpr int GSTAGES = 3;
constexpr int GEMM_SMEM = GSTAGES * 2 * GSTAGEB;   // 110592 B

template <int ADD>
__device__ __forceinline__ void gemm_body(const float* __restrict__ A,
                                          const float* __restrict__ B,
                                          float* __restrict__ C,
                                          int N, int K, int m0, int n0,
                                          float* smem) {
    float* sA = smem;                       // [3][GSTAGE]
    float* sB = smem + GSTAGES * GSTAGE;    // [3][GSTAGE]

    const int tid = threadIdx.x, lane = tid & 31, wid = tid >> 5;
    const int wm = wid & 3, wn = wid >> 2;

    const int sr = tid >> 3;
    const int sc = (tid & 7) * 4;
    const float* Ag = A + (size_t)(m0 + sr) * K + sc;
    const float* Bg = B + (size_t)(n0 + sr) * K + sc;
    const uint32_t sAu = sptr(sA) + (sr * GLDS + sc) * 4;
    const uint32_t sBu = sptr(sB) + (sr * GLDS + sc) * 4;

    float acc[2][8][4];
#pragma unroll
    for (int i = 0; i < 2; i++)
#pragma unroll
        for (int j = 0; j < 8; j++)
#pragma unroll
            for (int q = 0; q < 4; q++) acc[i][j][q] = 0.f;

    const int grp = lane >> 3, lr = lane & 7;
    const int a_row = wm * 32 + (grp & 1) * 8 + lr;
    const int a_col = (grp >> 1) * 4;
    const int b_row = wn * 64 + (grp >> 1) * 8 + lr;
    const int b_col = (grp & 1) * 4;

    const int nk = K / GBK;

    auto issue = [&](int stage, int kt) {
        const float* Ak = Ag + (size_t)kt * GBK;
        const float* Bk = Bg + (size_t)kt * GBK;
        uint32_t da = sAu + stage * GSTAGEB;
        uint32_t db = sBu + stage * GSTAGEB;
#pragma unroll
        for (int i = 0; i < 4; i++) {
            cp_async16(da + i * (32 * GLDS * 4), Ak + (size_t)(32 * i) * K);
            cp_async16(db + i * (32 * GLDS * 4), Bk + (size_t)(32 * i) * K);
        }
        cp_commit();
    };

    issue(0, 0);
    if (nk > 1) issue(1, 1);

    for (int kt = 0; kt < nk; ++kt) {
        if (kt + 1 < nk) cp_wait<1>(); else cp_wait<0>();
        __syncthreads();
        const int cur = kt % GSTAGES;
        float* cA = sA + cur * GSTAGE;
        float* cB = sB + cur * GSTAGE;
        const uint32_t aaddr = sptr(cA + a_row * GLDS + a_col);
        const uint32_t baddr = sptr(cB + b_row * GLDS + b_col);
#pragma unroll
        for (int ks = 0; ks < 4; ++ks) {
            uint32_t af[2][4];
            ldm_x4(af[0], aaddr + ks * 32);
            ldm_x4(af[1], aaddr + 16 * GLDS * 4 + ks * 32);
            uint32_t bf[4][4];
#pragma unroll
            for (int ntp = 0; ntp < 4; ++ntp)
                ldm_x4(bf[ntp], baddr + ntp * 16 * GLDS * 4 + ks * 32);
#pragma unroll
            for (int mt = 0; mt < 2; ++mt)
#pragma unroll
                for (int nt = 0; nt < 8; ++nt)
                    mma_tf32(acc[mt][nt], af[mt], &bf[nt >> 1][(nt & 1) * 2]);
        }
        if (kt + 2 < nk) issue((kt + 2) % GSTAGES, kt + 2);
    }

    const int row0 = m0 + wm * 32 + (lane >> 2);
    const int col0 = n0 + wn * 64 + (lane & 3) * 2;
#pragma unroll
    for (int mt = 0; mt < 2; ++mt)
#pragma unroll
        for (int nt = 0; nt < 8; ++nt) {
            int r = row0 + mt * 16;
            int c = col0 + nt * 8;
            float2* p0 = (float2*)&C[(size_t)r * N + c];
            float2* p1 = (float2*)&C[(size_t)(r + 8) * N + c];
            float2 v0 = make_float2(acc[mt][nt][0], acc[mt][nt][1]);
            float2 v1 = make_float2(acc[mt][nt][2], acc[mt][nt][3]);
            if (ADD) {
                float2 o0 = *p0, o1 = *p1;
                v0.x += o0.x; v0.y += o0.y; v1.x += o1.x; v1.y += o1.y;
            }
            *p0 = v0;
            *p1 = v1;
        }
}

template <int ADD>
__global__ __launch_bounds__(256, 2) void mma_nt_kernel(const float* __restrict__ A,
                                                        const float* __restrict__ B,
                                                        float* __restrict__ C,
                                                        int N, int K) {
    extern __shared__ float smem[];
    gemm_body<ADD>(A, B, C, N, K, blockIdx.y * GBM, blockIdx.x * GBN, smem);
}

// fused QKV: grid.x = 16 (q) + 8 (k) + 8 (v)
__global__ __launch_bounds__(256, 2) void mma_qkv_kernel(const float* __restrict__ A,
                                                         const float* __restrict__ qw,
                                                         const float* __restrict__ kw,
                                                         const float* __restrict__ vw,
                                                         float* __restrict__ q,
                                                         float* __restrict__ k,
                                                         float* __restrict__ v) {
    extern __shared__ float smem[];
    int bx = blockIdx.x;
    const float* B; float* C; int N, n0;
    if (bx < 16)      { B = qw; C = q; N = Hn * HDn;  n0 = bx * GBN; }
    else if (bx < 24) { B = kw; C = k; N = KVn * HDn; n0 = (bx - 16) * GBN; }
    else              { B = vw; C = v; N = KVn * HDn; n0 = (bx - 24) * GBN; }
    gemm_body<0>(A, B, C, N, Dn, blockIdx.y * GBM, n0, smem);
}

// fused gate+up
__global__ __launch_bounds__(256, 2) void mma_gu_kernel(const float* __restrict__ A,
                                                        const float* __restrict__ gw,
                                                        const float* __restrict__ uw,
                                                        float* __restrict__ g,
                                                        float* __restrict__ u) {
    extern __shared__ float smem[];
    int bx = blockIdx.x;
    const float* B; float* C; int n0;
    if (bx < 24) { B = gw; C = g; n0 = bx * GBN; }
    else         { B = uw; C = u; n0 = (bx - 24) * GBN; }
    gemm_body<0>(A, B, C, FFn, Dn, blockIdx.y * GBM, n0, smem);
}

// ---------------- TF32 MMA flash attention ----------------
constexpr int A_KS = 132;
constexpr int A_VS = 68;
constexpr int A_PS = 68;
constexpr int ATTN_SMEM = (64 * A_KS + 128 * A_VS + 64 * A_PS) * 4;  // 86016

__global__ __launch_bounds__(128) void attn_mma_kernel(const float* __restrict__ Q,
                                                       const float* __restrict__ Kb,
                                                       const float* __restrict__ Vb,
                                                       float* __restrict__ O) {
    extern __shared__ float sm[];
    float* sK = sm;
    float* sV = sm + 64 * A_KS;
    float* sP = sV + 128 * A_VS;

    const int h = blockIdx.y;
    const int qt0 = blockIdx.x * 64;
    const int kv = h >> 1;
    const float scale = 0.0883883476483184f;
    const int tid = threadIdx.x, lane = tid & 31, wid = tid >> 5;
    const int grp = lane >> 3, lr = lane & 7;
    const int r0 = lane >> 2, c0 = (lane & 3) * 2;

    const float* qbase = Q + (size_t)qt0 * (Hn * HDn) + (size_t)h * HDn;
#pragma unroll
    for (int r = 0; r < 16; ++r) {
        int idx = tid + r * 128;
        int row = idx >> 5, c4 = idx & 31;
        float4 v = *(const float4*)(qbase + (size_t)row * (Hn * HDn) + c4 * 4);
        uint4 u = make_uint4(f2tf(v.x * scale), f2tf(v.y * scale),
                             f2tf(v.z * scale), f2tf(v.w * scale));
        *(uint4*)&sK[row * A_KS + c4 * 4] = u;
    }
    __syncthreads();
    uint32_t qf[16][4];
    {
        uint32_t qaddr = sptr(sK + (wid * 16 + (grp & 1) * 8 + lr) * A_KS + (grp >> 1) * 4);
#pragma unroll
        for (int ks = 0; ks < 16; ++ks) ldm_x4(qf[ks], qaddr + ks * 32);
    }
    __syncthreads();

    float o[16][4];
#pragma unroll
    for (int i = 0; i < 16; i++)
#pragma unroll
        for (int j = 0; j < 4; j++) o[i][j] = 0.f;
    float mreg[2] = {-1e30f, -1e30f}, lreg[2] = {0.f, 0.f};

    const float* Kh = Kb + (size_t)kv * Tn * HDn;
    const float* Vh = Vb + (size_t)kv * Tn * HDn;
    const int nkt = (qt0 >> 6) + 1;

    float* myP = sP + wid * 16 * A_PS;
    const uint32_t kaddr = sptr(sK + ((grp >> 1) * 8 + lr) * A_KS + (grp & 1) * 4);
    const uint32_t paddr = sptr(myP + ((grp & 1) * 8 + lr) * A_PS + (grp >> 1) * 4);
    const uint32_t vaddr = sptr(sV + ((grp >> 1) * 8 + lr) * A_VS + (grp & 1) * 4);

    for (int kt = 0; kt < nkt; ++kt) {
        const int kt0 = kt << 6;
        if (kt) __syncthreads();
#pragma unroll
        for (int r = 0; r < 16; ++r) {
            int idx = tid + r * 128;
            int row = idx >> 5, c4 = idx & 31;
            float4 v = *(const float4*)(Kh + (size_t)(kt0 + row) * HDn + c4 * 4);
            uint4 u = make_uint4(f2tf(v.x), f2tf(v.y), f2tf(v.z), f2tf(v.w));
            *(uint4*)&sK[row * A_KS + c4 * 4] = u;
        }
        {
            const int d = tid;
#pragma unroll
            for (int rg = 0; rg < 16; ++rg) {
                float v0 = Vh[(size_t)(kt0 + rg * 4 + 0) * HDn + d];
                float v1 = Vh[(size_t)(kt0 + rg * 4 + 1) * HDn + d];
                float v2 = Vh[(size_t)(kt0 + rg * 4 + 2) * HDn + d];
                float v3 = Vh[(size_t)(kt0 + rg * 4 + 3) * HDn + d];
                uint4 u = make_uint4(f2tf(v0), f2tf(v1), f2tf(v2), f2tf(v3));
                *(uint4*)&sV[d * A_VS + rg * 4] = u;
            }
        }
        __syncthreads();

        float s[8][4];
#pragma unroll
        for (int i = 0; i < 8; i++)
#pragma unroll
            for (int j = 0; j < 4; j++) s[i][j] = 0.f;
#pragma unroll
        for (int ks = 0; ks < 16; ++ks) {
            uint32_t bf[4][4];
#pragma unroll
            for (int ntp = 0; ntp < 4; ++ntp)
                ldm_x4(bf[ntp], kaddr + (ntp * 16 * A_KS) * 4 + ks * 32);
#pragma unroll
            for (int nt = 0; nt < 8; ++nt)
                mma_tf32(s[nt], qf[ks], &bf[nt >> 1][(nt & 1) * 2]);
        }

        if (kt == nkt - 1) {
            int row0g = qt0 + wid * 16 + r0;
#pragma unroll
            for (int nt = 0; nt < 8; ++nt) {
                int colg = kt0 + nt * 8 + c0;
                if (colg > row0g)          s[nt][0] = -1e30f;
                if (colg + 1 > row0g)      s[nt][1] = -1e30f;
                if (colg > row0g + 8)      s[nt][2] = -1e30f;
                if (colg + 1 > row0g + 8)  s[nt][3] = -1e30f;
            }
        }

#pragma unroll
        for (int hf = 0; hf < 2; ++hf) {
            float rm = -1e30f;
#pragma unroll
            for (int nt = 0; nt < 8; ++nt)
                rm = fmaxf(rm, fmaxf(s[nt][2 * hf], s[nt][2 * hf + 1]));
            rm = fmaxf(rm, __shfl_xor_sync(0xffffffffu, rm, 1));
            rm = fmaxf(rm, __shfl_xor_sync(0xffffffffu, rm, 2));
            float mn = fmaxf(mreg[hf], rm);
            float corr = __expf(mreg[hf] - mn);
            mreg[hf] = mn;
            float su = 0.f;
#pragma unroll
            for (int nt = 0; nt < 8; ++nt) {
                float e0 = __expf(s[nt][2 * hf] - mn);
                float e1 = __expf(s[nt][2 * hf + 1] - mn);
                s[nt][2 * hf] = e0;
                s[nt][2 * hf + 1] = e1;
                su += e0 + e1;
            }
            su += __shfl_xor_sync(0xffffffffu, su, 1);
            su += __shfl_xor_sync(0xffffffffu, su, 2);
            lreg[hf] = lreg[hf] * corr + su;
#pragma unroll
            for (int nt = 0; nt < 16; ++nt) {
                o[nt][2 * hf] *= corr;
                o[nt][2 * hf + 1] *= corr;
            }
        }

#pragma unroll
        for (int nt = 0; nt < 8; ++nt) {
            *(uint2*)&myP[r0 * A_PS + nt * 8 + c0] =
                make_uint2(f2tf(s[nt][0]), f2tf(s[nt][1]));
            *(uint2*)&myP[(r0 + 8) * A_PS + nt * 8 + c0] =
                make_uint2(f2tf(s[nt][2]), f2tf(s[nt][3]));
        }
        __syncwarp();

#pragma unroll
        for (int ks = 0; ks < 8; ++ks) {
            uint32_t pf[4];
            ldm_x4(pf, paddr + ks * 32);
#pragma unroll
            for (int np = 0; np < 8; ++np) {
                uint32_t bf[4];
                ldm_x4(bf, vaddr + (np * 16 * A_VS) * 4 + ks * 32);
                mma_tf32(o[2 * np],     pf, &bf[0]);
                mma_tf32(o[2 * np + 1], pf, &bf[2]);
            }
        }
    }

    // epilogue: tf32-rounded (feeds O-projection GEMM via cp.async)
    float inv0 = 1.0f / lreg[0], inv1 = 1.0f / lreg[1];
    int row0g = qt0 + wid * 16 + r0;
#pragma unroll
    for (int nt = 0; nt < 16; ++nt) {
        size_t base = (size_t)h * HDn + nt * 8 + c0;
        *(float2*)&O[(size_t)row0g * (Hn * HDn) + base] =
            make_float2(f2tff(o[nt][0] * inv0), f2tff(o[nt][1] * inv0));
        *(float2*)&O[(size_t)(row0g + 8) * (Hn * HDn) + base] =
            make_float2(f2tff(o[nt][2] * inv1), f2tff(o[nt][3] * inv1));
    }
}

// ---------------- host orchestration ----------------
extern "C" void kernel_launch(void* const* d_in, const int* in_sizes, int n_in,
                              void* d_out, int out_size) {
    const float* emb = (const float*)d_in[0];
    const float* ln1 = (const float*)d_in[1];
    const float* qw  = (const float*)d_in[2];
    const float* kw  = (const float*)d_in[3];
    const float* vw  = (const float*)d_in[4];
    const float* qn  = (const float*)d_in[5];
    const float* kn  = (const float*)d_in[6];
    const float* ow  = (const float*)d_in[7];
    const float* ln2 = (const float*)d_in[8];
    const float* gw  = (const float*)d_in[9];
    const float* uw  = (const float*)d_in[10];
    const float* dw  = (const float*)d_in[11];
    const float* nw  = (const float*)d_in[12];

    float* out  = (float*)d_out;
    float* keys = out + (size_t)Tn * Dn;
    float* vals = keys + (size_t)Ln * KVn * Tn * HDn;

    float *ph, *px, *pq, *pao, *pkt, *pvt, *pg, *pu, *pwc;
    cudaGetSymbolAddress((void**)&ph,  g_h);
    cudaGetSymbolAddress((void**)&px,  g_x);
    cudaGetSymbolAddress((void**)&pq,  g_q);
    cudaGetSymbolAddress((void**)&pao, g_ao);
    cudaGetSymbolAddress((void**)&pkt, g_kt);
    cudaGetSymbolAddress((void**)&pvt, g_vt);
    cudaGetSymbolAddress((void**)&pg,  g_gate);
    cudaGetSymbolAddress((void**)&pu,  g_up);
    cudaGetSymbolAddress((void**)&pwc, g_wc);

    cudaFuncSetAttribute(attn_mma_kernel, cudaFuncAttributeMaxDynamicSharedMemorySize, ATTN_SMEM);
    cudaFuncSetAttribute(mma_nt_kernel<0>, cudaFuncAttributeMaxDynamicSharedMemorySize, GEMM_SMEM);
    cudaFuncSetAttribute(mma_nt_kernel<1>, cudaFuncAttributeMaxDynamicSharedMemorySize, GEMM_SMEM);
    cudaFuncSetAttribute(mma_qkv_kernel, cudaFuncAttributeMaxDynamicSharedMemorySize, GEMM_SMEM);
    cudaFuncSetAttribute(mma_gu_kernel, cudaFuncAttributeMaxDynamicSharedMemorySize, GEMM_SMEM);

    // pre-round weights to tf32 (consumed raw by cp.async GEMMs)
    {
        struct { const float* src; size_t off; size_t n; } cv[7] = {
            { qw, W_Q, (size_t)Ln * Hn * HDn * Dn },
            { kw, W_K, (size_t)Ln * KVn * HDn * Dn },
            { vw, W_V, (size_t)Ln * KVn * HDn * Dn },
            { ow, W_O, (size_t)Ln * Dn * Hn * HDn },
            { gw, W_G, (size_t)Ln * FFn * Dn },
            { uw, W_U, (size_t)Ln * FFn * Dn },
            { dw, W_D, (size_t)Ln * Dn * FFn },
        };
        for (int i = 0; i < 7; i++) {
            int n4 = (int)(cv[i].n / 4);
            conv_tf32_kernel<<<(n4 + 255) / 256, 256>>>(
                (const float4*)cv[i].src, (float4*)(pwc + cv[i].off), n4);
        }
    }

    cudaMemcpyAsync(ph, emb, sizeof(float) * Tn * Dn, cudaMemcpyDeviceToDevice);
    rope_tables_kernel<<<Tn, 64>>>();

    for (int i = 0; i < Ln; ++i) {
        rms_rows_kernel<1><<<Tn, 256>>>(ph, ln1 + (size_t)i * Dn, px);

        mma_qkv_kernel<<<dim3(32, Tn / GBM), 256, GEMM_SMEM>>>(
            px, pwc + W_Q + (size_t)i * (Hn * HDn) * Dn,
            pwc + W_K + (size_t)i * (KVn * HDn) * Dn,
            pwc + W_V + (size_t)i * (KVn * HDn) * Dn, pq, pkt, pvt);

        float* klayer = keys + (size_t)i * KVn * Tn * HDn;
        float* vlayer = vals + (size_t)i * KVn * Tn * HDn;

        qknorm_rope_kernel<<<dim3(Tn, Hn), 128>>>(pq, pq, qn + (size_t)i * HDn, Hn, 0);
        qknorm_rope_kernel<<<dim3(Tn, KVn), 128>>>(pkt, klayer, kn + (size_t)i * HDn, KVn, 1);
        v_transpose_kernel<<<(Tn * KVn * 32) / 256, 256>>>((const float4*)pvt, (float4*)vlayer);

        attn_mma_kernel<<<dim3(Tn / 64, Hn), 128, ATTN_SMEM>>>(pq, klayer, vlayer, pao);

        mma_nt_kernel<1><<<dim3(Dn / GBN, Tn / GBM), 256, GEMM_SMEM>>>(
            pao, pwc + W_O + (size_t)i * Dn * (Hn * HDn), ph, Dn, Hn * HDn);

        rms_rows_kernel<1><<<Tn, 256>>>(ph, ln2 + (size_t)i * Dn, px);
        mma_gu_kernel<<<dim3(48, Tn / GBM), 256, GEMM_SMEM>>>(
            px, pwc + W_G + (size_t)i * FFn * Dn, pwc + W_U + (size_t)i * FFn * Dn, pg, pu);
        silu_mul_kernel<<<(Tn * FFn / 4) / 256, 256>>>((float4*)pg, (const float4*)pu, Tn * FFn / 4);
        mma_nt_kernel<1><<<dim3(Dn / GBN, Tn / GBM), 256, GEMM_SMEM>>>(
            pg, pwc + W_D + (size_t)i * Dn * FFn, ph, Dn, FFn);
    }

    rms_rows_kernel<0><<<Tn, 256>>>(ph, nw, out);
}

// round 6
// speedup vs baseline: 4.7737x; 1.0325x over previous
#include <cuda_runtime.h>
#include <math.h>
#include <stdint.h>

// ---------------- problem constants ----------------
constexpr int Tn  = 2048;
constexpr int Dn  = 1024;
constexpr int Hn  = 16;
constexpr int KVn = 8;
constexpr int HDn = 128;
constexpr int FFn = 3072;
constexpr int Ln  = 5;
constexpr float EPSf = 1e-6f;

// ---------------- scratch ----------------
__device__ float g_h [Tn * Dn];
__device__ float g_x [Tn * Dn];
__device__ float g_q [Tn * Hn * HDn];
__device__ float g_ao[Tn * Hn * HDn];
__device__ float g_kt[Tn * KVn * HDn];
__device__ float g_gate[Tn * FFn];
__device__ float g_up  [Tn * FFn];
__device__ float g_cos[Tn * 64];
__device__ float g_sin[Tn * 64];

// tf32-rounded weight copies (one arena)
constexpr size_t W_Q  = 0;
constexpr size_t W_K  = W_Q + (size_t)Ln * Hn * HDn * Dn;
constexpr size_t W_V  = W_K + (size_t)Ln * KVn * HDn * Dn;
constexpr size_t W_O  = W_V + (size_t)Ln * KVn * HDn * Dn;
constexpr size_t W_G  = W_O + (size_t)Ln * Dn * Hn * HDn;
constexpr size_t W_U  = W_G + (size_t)Ln * FFn * Dn;
constexpr size_t W_D  = W_U + (size_t)Ln * FFn * Dn;
constexpr size_t W_TOT= W_D + (size_t)Ln * Dn * FFn;
__device__ float g_wc[W_TOT];

// ---------------- PTX helpers ----------------
__device__ __forceinline__ uint32_t sptr(const void* p) {
    return (uint32_t)__cvta_generic_to_shared(p);
}
__device__ __forceinline__ uint32_t f2tf(float f) {
    uint32_t u;
    asm("cvt.rna.tf32.f32 %0, %1;" : "=r"(u) : "f"(f));
    return u;
}
__device__ __forceinline__ float f2tff(float f) {
    return __uint_as_float(f2tf(f));
}
__device__ __forceinline__ void ldm_x4(uint32_t* r, uint32_t addr) {
    asm volatile("ldmatrix.sync.aligned.m8n8.x4.shared.b16 {%0,%1,%2,%3}, [%4];"
                 : "=r"(r[0]), "=r"(r[1]), "=r"(r[2]), "=r"(r[3]) : "r"(addr));
}
__device__ __forceinline__ void mma_tf32(float* c, const uint32_t* a, const uint32_t* b) {
    asm volatile("mma.sync.aligned.m16n8k8.row.col.f32.tf32.tf32.f32 "
                 "{%0,%1,%2,%3}, {%4,%5,%6,%7}, {%8,%9}, {%0,%1,%2,%3};"
                 : "+f"(c[0]), "+f"(c[1]), "+f"(c[2]), "+f"(c[3])
                 : "r"(a[0]), "r"(a[1]), "r"(a[2]), "r"(a[3]), "r"(b[0]), "r"(b[1]));
}
__device__ __forceinline__ void cp_async16(uint32_t dst, const void* src) {
    asm volatile("cp.async.ca.shared.global [%0], [%1], 16;" :: "r"(dst), "l"(src));
}
__device__ __forceinline__ void cp_commit() {
    asm volatile("cp.async.commit_group;" ::: "memory");
}
template <int N>
__device__ __forceinline__ void cp_wait() {
    asm volatile("cp.async.wait_group %0;" :: "n"(N) : "memory");
}

// ---------------- merged weight tf32 pre-round (7 segments, 1 kernel) ----------------
struct Cv7 {
    const float4* s[7];
    float4* d[7];
    int cum[8];
};
__global__ void conv7_kernel(Cv7 a) {
    int idx = blockIdx.x * 256 + threadIdx.x;
    if (idx >= a.cum[7]) return;
    int s = 0;
#pragma unroll
    for (int i = 0; i < 6; i++) s += (idx >= a.cum[i + 1]) ? 1 : 0;
    int off = idx - a.cum[s];
    float4 v = a.s[s][off];
    a.d[s][off] = make_float4(f2tff(v.x), f2tff(v.y), f2tff(v.z), f2tff(v.w));
}

// ---------------- RoPE tables ----------------
__global__ void rope_tables_kernel() {
    int t = blockIdx.x;
    int j = threadIdx.x;
    float inv = 1.0f / powf(1.0e6f, (float)j * (1.0f / 64.0f));
    float ang = (float)t * inv;
    g_cos[t * 64 + j] = cosf(ang);
    g_sin[t * 64 + j] = sinf(ang);
}

// ---------------- RMSNorm rows ----------------
template <int ROUND>
__global__ void rms_rows_kernel(const float* __restrict__ in,
                                const float* __restrict__ w,
                                float* __restrict__ out) {
    int t = blockIdx.x;
    const float4* ip = (const float4*)(in + (size_t)t * Dn);
    const float4* wp = (const float4*)w;
    float4 v = ip[threadIdx.x];
    float s = v.x * v.x + v.y * v.y + v.z * v.z + v.w * v.w;
#pragma unroll
    for (int off = 16; off; off >>= 1) s += __shfl_xor_sync(0xffffffffu, s, off);
    __shared__ float ws[8];
    if ((threadIdx.x & 31) == 0) ws[threadIdx.x >> 5] = s;
    __syncthreads();
    float tot = 0.f;
#pragma unroll
    for (int i = 0; i < 8; i++) tot += ws[i];
    float r = rsqrtf(tot * (1.0f / (float)Dn) + EPSf);
    float4 wv = wp[threadIdx.x];
    float4 o = make_float4(v.x * r * wv.x, v.y * r * wv.y, v.z * r * wv.z, v.w * r * wv.w);
    if (ROUND) o = make_float4(f2tff(o.x), f2tff(o.y), f2tff(o.z), f2tff(o.w));
    ((float4*)(out + (size_t)t * Dn))[threadIdx.x] = o;
}

// ---------------- combined Q/K per-head RMSNorm + RoPE ----------------
// grid (Tn, Hn+KVn): h<Hn -> Q in place; else K -> klayer transposed [KV][T][HD]
__global__ void qknorm_rope_kernel(float* __restrict__ q,
                                   const float* __restrict__ k,
                                   float* __restrict__ ko,
                                   const float* __restrict__ qw,
                                   const float* __restrict__ kw) {
    int t = blockIdx.x, h = blockIdx.y, d = threadIdx.x;
    bool isq = h < Hn;
    const float* row = isq ? (q + ((size_t)t * Hn + h) * HDn)
                           : (k + ((size_t)t * KVn + (h - Hn)) * HDn);
    const float* w = isq ? qw : kw;
    float v = row[d];
    float s = v * v;
#pragma unroll
    for (int off = 16; off; off >>= 1) s += __shfl_xor_sync(0xffffffffu, s, off);
    __shared__ float ws[4];
    if ((d & 31) == 0) ws[d >> 5] = s;
    __syncthreads();
    float tot = ws[0] + ws[1] + ws[2] + ws[3];
    float r = rsqrtf(tot * (1.0f / (float)HDn) + EPSf);
    float xn = v * r * w[d];
    __shared__ float sh[128];
    sh[d] = xn;
    __syncthreads();
    float other = (d < 64) ? -sh[d + 64] : sh[d - 64];
    int j = d & 63;
    float c = g_cos[t * 64 + j];
    float sn = g_sin[t * 64 + j];
    float o = xn * c + other * sn;
    if (isq) q[((size_t)t * Hn + h) * HDn + d] = o;
    else     ko[((size_t)(h - Hn) * Tn + t) * HDn + d] = o;
}

// ---------------- silu(g)*u (emit tf32) ----------------
__global__ void silu_mul_kernel(float4* __restrict__ g, const float4* __restrict__ u, int n4) {
    int idx = blockIdx.x * blockDim.x + threadIdx.x;
    if (idx < n4) {
        float4 gv = g[idx], uv = u[idx];
        gv.x = f2tff(gv.x / (1.0f + __expf(-gv.x)) * uv.x);
        gv.y = f2tff(gv.y / (1.0f + __expf(-gv.y)) * uv.y);
        gv.z = f2tff(gv.z / (1.0f + __expf(-gv.z)) * uv.z);
        gv.w = f2tff(gv.w / (1.0f + __expf(-gv.w)) * uv.w);
        g[idx] = gv;
    }
}

// ---------------- TF32 tensor-core GEMM NT (cp.async 3-stage) ----------------
constexpr int GBM = 128, GBK = 32, GPAD = 4, GLDS = GBK + GPAD;
constexpr int GSTAGES = 3;
constexpr int ASTAGE  = GBM * GLDS;
#define GEMM_SMEM_BN(BN) (GSTAGES * (GBM + (BN)) * GLDS * 4)

// TRANSV: write C transposed as [col/128][row][col%128] (V into vals buffer)
template <int ADD, int BN, int TRANSV>
__device__ __forceinline__ void gemm_body(const float* __restrict__ A,
                                          const float* __restrict__ B,
                                          float* __restrict__ C,
                                          int N, int K, int m0, int n0,
                                          float* smem) {
    constexpr int NWN = BN / 16;       // n micro-tiles per warp
    constexpr int NTP = BN / 32;       // B ldmatrix groups
    constexpr int BSTAGE = BN * GLDS;  // floats per B stage
    float* sA = smem;
    float* sB = smem + GSTAGES * ASTAGE;

    const int tid = threadIdx.x, lane = tid & 31, wid = tid >> 5;
    const int wm = wid & 3, wn = wid >> 2;

    const int sr = tid >> 3;
    const int sc = (tid & 7) * 4;
    const float* Ag = A + (size_t)(m0 + sr) * K + sc;
    const float* Bg = B + (size_t)(n0 + sr) * K + sc;
    const uint32_t sAu = sptr(sA) + (sr * GLDS + sc) * 4;
    const uint32_t sBu = sptr(sB) + (sr * GLDS + sc) * 4;

    float acc[2][NWN][4];
#pragma unroll
    for (int i = 0; i < 2; i++)
#pragma unroll
        for (int j = 0; j < NWN; j++)
#pragma unroll
            for (int q = 0; q < 4; q++) acc[i][j][q] = 0.f;

    const int grp = lane >> 3, lr = lane & 7;
    const int a_row = wm * 32 + (grp & 1) * 8 + lr;
    const int a_col = (grp >> 1) * 4;
    const int b_row = wn * (BN / 2) + (grp >> 1) * 8 + lr;
    const int b_col = (grp & 1) * 4;

    const int nk = K / GBK;

    auto issue = [&](int stage, int kt) {
        const float* Ak = Ag + (size_t)kt * GBK;
        const float* Bk = Bg + (size_t)kt * GBK;
        uint32_t da = sAu + stage * (ASTAGE * 4);
        uint32_t db = sBu + stage * (BSTAGE * 4);
#pragma unroll
        for (int i = 0; i < 4; i++)
            cp_async16(da + i * (32 * GLDS * 4), Ak + (size_t)(32 * i) * K);
#pragma unroll
        for (int i = 0; i < BN / 32; i++)
            cp_async16(db + i * (32 * GLDS * 4), Bk + (size_t)(32 * i) * K);
        cp_commit();
    };

    issue(0, 0);
    if (nk > 1) issue(1, 1);

    for (int kt = 0; kt < nk; ++kt) {
        if (kt + 1 < nk) cp_wait<1>(); else cp_wait<0>();
        __syncthreads();
        const int cur = kt % GSTAGES;
        float* cA = sA + cur * ASTAGE;
        float* cB = sB + cur * BSTAGE;
        const uint32_t aaddr = sptr(cA + a_row * GLDS + a_col);
        const uint32_t baddr = sptr(cB + b_row * GLDS + b_col);
#pragma unroll
        for (int ks = 0; ks < 4; ++ks) {
            uint32_t af[2][4];
            ldm_x4(af[0], aaddr + ks * 32);
            ldm_x4(af[1], aaddr + 16 * GLDS * 4 + ks * 32);
            uint32_t bf[NTP][4];
#pragma unroll
            for (int ntp = 0; ntp < NTP; ++ntp)
                ldm_x4(bf[ntp], baddr + ntp * 16 * GLDS * 4 + ks * 32);
#pragma unroll
            for (int mt = 0; mt < 2; ++mt)
#pragma unroll
                for (int nt = 0; nt < NWN; ++nt)
                    mma_tf32(acc[mt][nt], af[mt], &bf[nt >> 1][(nt & 1) * 2]);
        }
        if (kt + 2 < nk) issue((kt + 2) % GSTAGES, kt + 2);
    }

    const int row0 = m0 + wm * 32 + (lane >> 2);
    const int col0 = n0 + wn * (BN / 2) + (lane & 3) * 2;
#pragma unroll
    for (int mt = 0; mt < 2; ++mt)
#pragma unroll
        for (int nt = 0; nt < NWN; ++nt) {
            int r = row0 + mt * 16;
            int c = col0 + nt * 8;
            float2 v0 = make_float2(acc[mt][nt][0], acc[mt][nt][1]);
            float2 v1 = make_float2(acc[mt][nt][2], acc[mt][nt][3]);
            if (TRANSV) {
                size_t i0 = ((size_t)(c >> 7) * Tn + r) * HDn + (c & 127);
                size_t i1 = ((size_t)(c >> 7) * Tn + (r + 8)) * HDn + (c & 127);
                *(float2*)&C[i0] = v0;
                *(float2*)&C[i1] = v1;
            } else {
                float2* p0 = (float2*)&C[(size_t)r * N + c];
                float2* p1 = (float2*)&C[(size_t)(r + 8) * N + c];
                if (ADD) {
                    float2 o0 = *p0, o1 = *p1;
                    v0.x += o0.x; v0.y += o0.y; v1.x += o1.x; v1.y += o1.y;
                }
                *p0 = v0;
                *p1 = v1;
            }
        }
}

template <int ADD, int BN>
__global__ __launch_bounds__(256, 2) void mma_nt_kernel(const float* __restrict__ A,
                                                        const float* __restrict__ B,
                                                        float* __restrict__ C,
                                                        int N, int K) {
    extern __shared__ float smem[];
    gemm_body<ADD, BN, 0>(A, B, C, N, K, blockIdx.y * GBM, blockIdx.x * BN, smem);
}

// fused QKV: grid.x = 16 (q) + 8 (k) + 8 (v); v written transposed into vals
__global__ __launch_bounds__(256, 2) void mma_qkv_kernel(const float* __restrict__ A,
                                                         const float* __restrict__ qw,
                                                         const float* __restrict__ kw,
                                                         const float* __restrict__ vw,
                                                         float* __restrict__ q,
                                                         float* __restrict__ k,
                                                         float* __restrict__ vlayer) {
    extern __shared__ float smem[];
    int bx = blockIdx.x;
    int m0 = blockIdx.y * GBM;
    if (bx < 16) {
        gemm_body<0, 128, 0>(A, qw, q, Hn * HDn, Dn, m0, bx * 128, smem);
    } else if (bx < 24) {
        gemm_body<0, 128, 0>(A, kw, k, KVn * HDn, Dn, m0, (bx - 16) * 128, smem);
    } else {
        gemm_body<0, 128, 1>(A, vw, vlayer, KVn * HDn, Dn, m0, (bx - 24) * 128, smem);
    }
}

// fused gate+up
__global__ __launch_bounds__(256, 2) void mma_gu_kernel(const float* __restrict__ A,
                                                        const float* __restrict__ gw,
                                                        const float* __restrict__ uw,
                                                        float* __restrict__ g,
                                                        float* __restrict__ u) {
    extern __shared__ float smem[];
    int bx = blockIdx.x;
    const float* B; float* C; int n0;
    if (bx < 24) { B = gw; C = g; n0 = bx * 128; }
    else         { B = uw; C = u; n0 = (bx - 24) * 128; }
    gemm_body<0, 128, 0>(A, B, C, FFn, Dn, blockIdx.y * GBM, n0, smem);
}

// ---------------- TF32 MMA flash attention: 128 q-rows, 8 warps ----------------
constexpr int A_KS = 132;
constexpr int A_VS = 68;
constexpr int A_PS = 68;
constexpr int ATTN_SMEM = (64 * A_KS + 128 * A_VS + 128 * A_PS) * 4;  // 103424

__global__ __launch_bounds__(256) void attn_mma_kernel(const float* __restrict__ Q,
                                                       const float* __restrict__ Kb,
                                                       const float* __restrict__ Vb,
                                                       float* __restrict__ O) {
    extern __shared__ float sm[];
    float* sK = sm;                     // [64][132]: Q staging chunks, then K tiles
    float* sV = sm + 64 * A_KS;         // [128][68]: V transposed (d-major)
    float* sP = sV + 128 * A_VS;        // [128][68]: P (per-warp 16-row slices)

    const int h = blockIdx.y;
    const int qt0 = (gridDim.x - 1 - blockIdx.x) * 128;  // heavy tiles first
    const int kv = h >> 1;
    const float scale = 0.0883883476483184f;
    const int tid = threadIdx.x, lane = tid & 31, wid = tid >> 5;
    const int grp = lane >> 3, lr = lane & 7;
    const int r0 = lane >> 2, c0 = (lane & 3) * 2;

    // ---- stage Q (scaled, tf32) in two 64-row chunks through sK ----
    uint32_t qf[16][4];
#pragma unroll
    for (int ch = 0; ch < 2; ++ch) {
        __syncthreads();
        const float* qb = Q + (size_t)(qt0 + ch * 64) * (Hn * HDn) + (size_t)h * HDn;
#pragma unroll
        for (int r = 0; r < 8; ++r) {
            int idx = tid + r * 256;
            int row = idx >> 5, c4 = idx & 31;
            float4 v = *(const float4*)(qb + (size_t)row * (Hn * HDn) + c4 * 4);
            uint4 u = make_uint4(f2tf(v.x * scale), f2tf(v.y * scale),
                                 f2tf(v.z * scale), f2tf(v.w * scale));
            *(uint4*)&sK[row * A_KS + c4 * 4] = u;
        }
        __syncthreads();
        if ((wid >> 2) == ch) {
            uint32_t qaddr = sptr(sK + ((wid & 3) * 16 + (grp & 1) * 8 + lr) * A_KS + (grp >> 1) * 4);
#pragma unroll
            for (int ks = 0; ks < 16; ++ks) ldm_x4(qf[ks], qaddr + ks * 32);
        }
    }
    __syncthreads();

    float o[16][4];
#pragma unroll
    for (int i = 0; i < 16; i++)
#pragma unroll
        for (int j = 0; j < 4; j++) o[i][j] = 0.f;
    float mreg[2] = {-1e30f, -1e30f}, lreg[2] = {0.f, 0.f};

    const float* Kh = Kb + (size_t)kv * Tn * HDn;
    const float* Vh = Vb + (size_t)kv * Tn * HDn;
    const int nkt = (qt0 >> 6) + 2;

    float* myP = sP + wid * 16 * A_PS;
    const uint32_t kaddr = sptr(sK + ((grp >> 1) * 8 + lr) * A_KS + (grp & 1) * 4);
    const uint32_t paddr = sptr(myP + ((grp & 1) * 8 + lr) * A_PS + (grp >> 1) * 4);
    const uint32_t vaddr = sptr(sV + ((grp >> 1) * 8 + lr) * A_VS + (grp & 1) * 4);

    for (int kt = 0; kt < nkt; ++kt) {
        const int kt0 = kt << 6;
        if (kt) __syncthreads();
        // stage K natural [kpos][d]
#pragma unroll
        for (int r = 0; r < 8; ++r) {
            int idx = tid + r * 256;
            int row = idx >> 5, c4 = idx & 31;
            float4 v = *(const float4*)(Kh + (size_t)(kt0 + row) * HDn + c4 * 4);
            uint4 u = make_uint4(f2tf(v.x), f2tf(v.y), f2tf(v.z), f2tf(v.w));
            *(uint4*)&sK[row * A_KS + c4 * 4] = u;
        }
        // stage V transposed [d][kpos]; 256 threads: 2 halves of kpos
        {
            const int d = tid & 127, half = tid >> 7;
#pragma unroll
            for (int rg = 0; rg < 8; ++rg) {
                int kp = half * 32 + rg * 4;
                float v0 = Vh[(size_t)(kt0 + kp + 0) * HDn + d];
                float v1 = Vh[(size_t)(kt0 + kp + 1) * HDn + d];
                float v2 = Vh[(size_t)(kt0 + kp + 2) * HDn + d];
                float v3 = Vh[(size_t)(kt0 + kp + 3) * HDn + d];
                uint4 u = make_uint4(f2tf(v0), f2tf(v1), f2tf(v2), f2tf(v3));
                *(uint4*)&sV[d * A_VS + kp] = u;
            }
        }
        __syncthreads();

        // ---- S = Q @ K^T (per warp: 16 rows x 64 cols) ----
        float s[8][4];
#pragma unroll
        for (int i = 0; i < 8; i++)
#pragma unroll
            for (int j = 0; j < 4; j++) s[i][j] = 0.f;
#pragma unroll
        for (int ks = 0; ks < 16; ++ks) {
            uint32_t bf[4][4];
#pragma unroll
            for (int ntp = 0; ntp < 4; ++ntp)
                ldm_x4(bf[ntp], kaddr + (ntp * 16 * A_KS) * 4 + ks * 32);
#pragma unroll
            for (int nt = 0; nt < 8; ++nt)
                mma_tf32(s[nt], qf[ks], &bf[nt >> 1][(nt & 1) * 2]);
        }

        // causal mask — only the last two k-tiles can intersect the diagonal
        if (kt >= nkt - 2) {
            int rowg = qt0 + wid * 16 + r0;
#pragma unroll
            for (int nt = 0; nt < 8; ++nt) {
                int colg = kt0 + nt * 8 + c0;
                if (colg > rowg)          s[nt][0] = -1e30f;
                if (colg + 1 > rowg)      s[nt][1] = -1e30f;
                if (colg > rowg + 8)      s[nt][2] = -1e30f;
                if (colg + 1 > rowg + 8)  s[nt][3] = -1e30f;
            }
        }

        // ---- online softmax ----
#pragma unroll
        for (int hf = 0; hf < 2; ++hf) {
            float rm = -1e30f;
#pragma unroll
            for (int nt = 0; nt < 8; ++nt)
                rm = fmaxf(rm, fmaxf(s[nt][2 * hf], s[nt][2 * hf + 1]));
            rm = fmaxf(rm, __shfl_xor_sync(0xffffffffu, rm, 1));
            rm = fmaxf(rm, __shfl_xor_sync(0xffffffffu, rm, 2));
            float mn = fmaxf(mreg[hf], rm);
            float corr = __expf(mreg[hf] - mn);
            mreg[hf] = mn;
            float su = 0.f;
#pragma unroll
            for (int nt = 0; nt < 8; ++nt) {
                float e0 = __expf(s[nt][2 * hf] - mn);
                float e1 = __expf(s[nt][2 * hf + 1] - mn);
                s[nt][2 * hf] = e0;
                s[nt][2 * hf + 1] = e1;
                su += e0 + e1;
            }
            su += __shfl_xor_sync(0xffffffffu, su, 1);
            su += __shfl_xor_sync(0xffffffffu, su, 2);
            lreg[hf] = lreg[hf] * corr + su;
#pragma unroll
            for (int nt = 0; nt < 16; ++nt) {
                o[nt][2 * hf] *= corr;
                o[nt][2 * hf + 1] *= corr;
            }
        }

        // ---- P to warp-private smem (tf32) ----
#pragma unroll
        for (int nt = 0; nt < 8; ++nt) {
            *(uint2*)&myP[r0 * A_PS + nt * 8 + c0] =
                make_uint2(f2tf(s[nt][0]), f2tf(s[nt][1]));
            *(uint2*)&myP[(r0 + 8) * A_PS + nt * 8 + c0] =
                make_uint2(f2tf(s[nt][2]), f2tf(s[nt][3]));
        }
        __syncwarp();

        // ---- O += P @ V ----
#pragma unroll
        for (int ks = 0; ks < 8; ++ks) {
            uint32_t pf[4];
            ldm_x4(pf, paddr + ks * 32);
#pragma unroll
            for (int np = 0; np < 8; ++np) {
                uint32_t bf[4];
                ldm_x4(bf, vaddr + (np * 16 * A_VS) * 4 + ks * 32);
                mma_tf32(o[2 * np],     pf, &bf[0]);
                mma_tf32(o[2 * np + 1], pf, &bf[2]);
            }
        }
    }

    // ---- epilogue: tf32-rounded (feeds O-projection via cp.async) ----
    float inv0 = 1.0f / lreg[0], inv1 = 1.0f / lreg[1];
    int rowg = qt0 + wid * 16 + r0;
#pragma unroll
    for (int nt = 0; nt < 16; ++nt) {
        size_t base = (size_t)h * HDn + nt * 8 + c0;
        *(float2*)&O[(size_t)rowg * (Hn * HDn) + base] =
            make_float2(f2tff(o[nt][0] * inv0), f2tff(o[nt][1] * inv0));
        *(float2*)&O[(size_t)(rowg + 8) * (Hn * HDn) + base] =
            make_float2(f2tff(o[nt][2] * inv1), f2tff(o[nt][3] * inv1));
    }
}

// ---------------- host orchestration ----------------
extern "C" void kernel_launch(void* const* d_in, const int* in_sizes, int n_in,
                              void* d_out, int out_size) {
    const float* emb = (const float*)d_in[0];
    const float* ln1 = (const float*)d_in[1];
    const float* qw  = (const float*)d_in[2];
    const float* kw  = (const float*)d_in[3];
    const float* vw  = (const float*)d_in[4];
    const float* qn  = (const float*)d_in[5];
    const float* kn  = (const float*)d_in[6];
    const float* ow  = (const float*)d_in[7];
    const float* ln2 = (const float*)d_in[8];
    const float* gw  = (const float*)d_in[9];
    const float* uw  = (const float*)d_in[10];
    const float* dw  = (const float*)d_in[11];
    const float* nw  = (const float*)d_in[12];

    float* out  = (float*)d_out;
    float* keys = out + (size_t)Tn * Dn;
    float* vals = keys + (size_t)Ln * KVn * Tn * HDn;

    float *ph, *px, *pq, *pao, *pkt, *pg, *pu, *pwc;
    cudaGetSymbolAddress((void**)&ph,  g_h);
    cudaGetSymbolAddress((void**)&px,  g_x);
    cudaGetSymbolAddress((void**)&pq,  g_q);
    cudaGetSymbolAddress((void**)&pao, g_ao);
    cudaGetSymbolAddress((void**)&pkt, g_kt);
    cudaGetSymbolAddress((void**)&pg,  g_gate);
    cudaGetSymbolAddress((void**)&pu,  g_up);
    cudaGetSymbolAddress((void**)&pwc, g_wc);

    cudaFuncSetAttribute(attn_mma_kernel, cudaFuncAttributeMaxDynamicSharedMemorySize, ATTN_SMEM);
    cudaFuncSetAttribute(mma_nt_kernel<1, 64>, cudaFuncAttributeMaxDynamicSharedMemorySize, GEMM_SMEM_BN(64));
    cudaFuncSetAttribute(mma_qkv_kernel, cudaFuncAttributeMaxDynamicSharedMemorySize, GEMM_SMEM_BN(128));
    cudaFuncSetAttribute(mma_gu_kernel, cudaFuncAttributeMaxDynamicSharedMemorySize, GEMM_SMEM_BN(128));

    // pre-round all weights to tf32, one kernel
    {
        Cv7 a;
        size_t offs[7] = { W_Q, W_K, W_V, W_O, W_G, W_U, W_D };
        const float* srcs[7] = { qw, kw, vw, ow, gw, uw, dw };
        size_t ns[7] = {
            (size_t)Ln * Hn * HDn * Dn, (size_t)Ln * KVn * HDn * Dn,
            (size_t)Ln * KVn * HDn * Dn, (size_t)Ln * Dn * Hn * HDn,
            (size_t)Ln * FFn * Dn, (size_t)Ln * FFn * Dn, (size_t)Ln * Dn * FFn };
        int cum = 0;
        for (int i = 0; i < 7; i++) {
            a.s[i] = (const float4*)srcs[i];
            a.d[i] = (float4*)(pwc + offs[i]);
            a.cum[i] = cum;
            cum += (int)(ns[i] / 4);
        }
        a.cum[7] = cum;
        conv7_kernel<<<(cum + 255) / 256, 256>>>(a);
    }

    cudaMemcpyAsync(ph, emb, sizeof(float) * Tn * Dn, cudaMemcpyDeviceToDevice);
    rope_tables_kernel<<<Tn, 64>>>();

    for (int i = 0; i < Ln; ++i) {
        float* klayer = keys + (size_t)i * KVn * Tn * HDn;
        float* vlayer = vals + (size_t)i * KVn * Tn * HDn;

        rms_rows_kernel<1><<<Tn, 256>>>(ph, ln1 + (size_t)i * Dn, px);

        mma_qkv_kernel<<<dim3(32, Tn / GBM), 256, GEMM_SMEM_BN(128)>>>(
            px, pwc + W_Q + (size_t)i * (Hn * HDn) * Dn,
            pwc + W_K + (size_t)i * (KVn * HDn) * Dn,
            pwc + W_V + (size_t)i * (KVn * HDn) * Dn, pq, pkt, vlayer);

        qknorm_rope_kernel<<<dim3(Tn, Hn + KVn), 128>>>(
            pq, pkt, klayer, qn + (size_t)i * HDn, kn + (size_t)i * HDn);

        attn_mma_kernel<<<dim3(Tn / 128, Hn), 256, ATTN_SMEM>>>(pq, klayer, vlayer, pao);

        mma_nt_kernel<1, 64><<<dim3(Dn / 64, Tn / GBM), 256, GEMM_SMEM_BN(64)>>>(
            pao, pwc + W_O + (size_t)i * Dn * (Hn * HDn), ph, Dn, Hn * HDn);

        rms_rows_kernel<1><<<Tn, 256>>>(ph, ln2 + (size_t)i * Dn, px);
        mma_gu_kernel<<<dim3(48, Tn / GBM), 256, GEMM_SMEM_BN(128)>>>(
            px, pwc + W_G + (size_t)i * FFn * Dn, pwc + W_U + (size_t)i * FFn * Dn, pg, pu);
        silu_mul_kernel<<<(Tn * FFn / 4) / 256, 256>>>((float4*)pg, (const float4*)pu, Tn * FFn / 4);
        mma_nt_kernel<1, 64><<<dim3(Dn / 64, Tn / GBM), 256, GEMM_SMEM_BN(64)>>>(
            pg, pwc + W_D + (size_t)i * Dn * FFn, ph, Dn, FFn);
    }

    rms_rows_kernel<0><<<Tn, 256>>>(ph, nw, out);
}

// round 7
// speedup vs baseline: 4.7842x; 1.0022x over previous
#include <cuda_runtime.h>
#include <math.h>
#include <stdint.h>

// ---------------- problem constants ----------------
constexpr int Tn  = 2048;
constexpr int Dn  = 1024;
constexpr int Hn  = 16;
constexpr int KVn = 8;
constexpr int HDn = 128;
constexpr int FFn = 3072;
constexpr int Ln  = 5;
constexpr float EPSf = 1e-6f;

// ---------------- scratch ----------------
__device__ float g_h [Tn * Dn];
__device__ float g_x [Tn * Dn];
__device__ float g_q [Tn * Hn * HDn];
__device__ float g_ao[Tn * Hn * HDn];
__device__ float g_kt[Tn * KVn * HDn];
__device__ float g_gate[Tn * FFn];
__device__ float g_up  [Tn * FFn];
__device__ float g_cos[Tn * 64];
__device__ float g_sin[Tn * 64];

// tf32-rounded weight copies (one arena)
constexpr size_t W_Q  = 0;
constexpr size_t W_K  = W_Q + (size_t)Ln * Hn * HDn * Dn;
constexpr size_t W_V  = W_K + (size_t)Ln * KVn * HDn * Dn;
constexpr size_t W_O  = W_V + (size_t)Ln * KVn * HDn * Dn;
constexpr size_t W_G  = W_O + (size_t)Ln * Dn * Hn * HDn;
constexpr size_t W_U  = W_G + (size_t)Ln * FFn * Dn;
constexpr size_t W_D  = W_U + (size_t)Ln * FFn * Dn;
constexpr size_t W_TOT= W_D + (size_t)Ln * Dn * FFn;
__device__ float g_wc[W_TOT];

// ---------------- PTX helpers ----------------
__device__ __forceinline__ uint32_t sptr(const void* p) {
    return (uint32_t)__cvta_generic_to_shared(p);
}
__device__ __forceinline__ uint32_t f2tf(float f) {
    uint32_t u;
    asm("cvt.rna.tf32.f32 %0, %1;" : "=r"(u) : "f"(f));
    return u;
}
__device__ __forceinline__ float f2tff(float f) {
    return __uint_as_float(f2tf(f));
}
__device__ __forceinline__ void ldm_x4(uint32_t* r, uint32_t addr) {
    asm volatile("ldmatrix.sync.aligned.m8n8.x4.shared.b16 {%0,%1,%2,%3}, [%4];"
                 : "=r"(r[0]), "=r"(r[1]), "=r"(r[2]), "=r"(r[3]) : "r"(addr));
}
__device__ __forceinline__ void mma_tf32(float* c, const uint32_t* a, const uint32_t* b) {
    asm volatile("mma.sync.aligned.m16n8k8.row.col.f32.tf32.tf32.f32 "
                 "{%0,%1,%2,%3}, {%4,%5,%6,%7}, {%8,%9}, {%0,%1,%2,%3};"
                 : "+f"(c[0]), "+f"(c[1]), "+f"(c[2]), "+f"(c[3])
                 : "r"(a[0]), "r"(a[1]), "r"(a[2]), "r"(a[3]), "r"(b[0]), "r"(b[1]));
}
__device__ __forceinline__ void cp_async16(uint32_t dst, const void* src) {
    asm volatile("cp.async.ca.shared.global [%0], [%1], 16;" :: "r"(dst), "l"(src));
}
__device__ __forceinline__ void cp_commit() {
    asm volatile("cp.async.commit_group;" ::: "memory");
}
template <int N>
__device__ __forceinline__ void cp_wait() {
    asm volatile("cp.async.wait_group %0;" :: "n"(N) : "memory");
}

// ---------------- merged weight tf32 pre-round (7 segments, 1 kernel) ----------------
struct Cv7 {
    const float4* s[7];
    float4* d[7];
    int cum[8];
};
__global__ void conv7_kernel(Cv7 a) {
    int idx = blockIdx.x * 256 + threadIdx.x;
    if (idx >= a.cum[7]) return;
    int s = 0;
#pragma unroll
    for (int i = 0; i < 6; i++) s += (idx >= a.cum[i + 1]) ? 1 : 0;
    int off = idx - a.cum[s];
    float4 v = a.s[s][off];
    a.d[s][off] = make_float4(f2tff(v.x), f2tff(v.y), f2tff(v.z), f2tff(v.w));
}

// ---------------- RoPE tables ----------------
__global__ void rope_tables_kernel() {
    int t = blockIdx.x;
    int j = threadIdx.x;
    float inv = 1.0f / powf(1.0e6f, (float)j * (1.0f / 64.0f));
    float ang = (float)t * inv;
    g_cos[t * 64 + j] = cosf(ang);
    g_sin[t * 64 + j] = sinf(ang);
}

// ---------------- RMSNorm rows ----------------
template <int ROUND>
__global__ void rms_rows_kernel(const float* __restrict__ in,
                                const float* __restrict__ w,
                                float* __restrict__ out) {
    int t = blockIdx.x;
    const float4* ip = (const float4*)(in + (size_t)t * Dn);
    const float4* wp = (const float4*)w;
    float4 v = ip[threadIdx.x];
    float s = v.x * v.x + v.y * v.y + v.z * v.z + v.w * v.w;
#pragma unroll
    for (int off = 16; off; off >>= 1) s += __shfl_xor_sync(0xffffffffu, s, off);
    __shared__ float ws[8];
    if ((threadIdx.x & 31) == 0) ws[threadIdx.x >> 5] = s;
    __syncthreads();
    float tot = 0.f;
#pragma unroll
    for (int i = 0; i < 8; i++) tot += ws[i];
    float r = rsqrtf(tot * (1.0f / (float)Dn) + EPSf);
    float4 wv = wp[threadIdx.x];
    float4 o = make_float4(v.x * r * wv.x, v.y * r * wv.y, v.z * r * wv.z, v.w * r * wv.w);
    if (ROUND) o = make_float4(f2tff(o.x), f2tff(o.y), f2tff(o.z), f2tff(o.w));
    ((float4*)(out + (size_t)t * Dn))[threadIdx.x] = o;
}

// ---------------- combined Q/K per-head RMSNorm + RoPE ----------------
// grid (Tn, Hn+KVn): h<Hn -> Q in place; else K -> klayer transposed [KV][T][HD]
__global__ void qknorm_rope_kernel(float* __restrict__ q,
                                   const float* __restrict__ k,
                                   float* __restrict__ ko,
                                   const float* __restrict__ qw,
                                   const float* __restrict__ kw) {
    int t = blockIdx.x, h = blockIdx.y, d = threadIdx.x;
    bool isq = h < Hn;
    const float* row = isq ? (q + ((size_t)t * Hn + h) * HDn)
                           : (k + ((size_t)t * KVn + (h - Hn)) * HDn);
    const float* w = isq ? qw : kw;
    float v = row[d];
    float s = v * v;
#pragma unroll
    for (int off = 16; off; off >>= 1) s += __shfl_xor_sync(0xffffffffu, s, off);
    __shared__ float ws[4];
    if ((d & 31) == 0) ws[d >> 5] = s;
    __syncthreads();
    float tot = ws[0] + ws[1] + ws[2] + ws[3];
    float r = rsqrtf(tot * (1.0f / (float)HDn) + EPSf);
    float xn = v * r * w[d];
    __shared__ float sh[128];
    sh[d] = xn;
    __syncthreads();
    float other = (d < 64) ? -sh[d + 64] : sh[d - 64];
    int j = d & 63;
    float c = g_cos[t * 64 + j];
    float sn = g_sin[t * 64 + j];
    float o = xn * c + other * sn;
    if (isq) q[((size_t)t * Hn + h) * HDn + d] = o;
    else     ko[((size_t)(h - Hn) * Tn + t) * HDn + d] = o;
}

// ---------------- silu(g)*u (emit tf32) ----------------
__global__ void silu_mul_kernel(float4* __restrict__ g, const float4* __restrict__ u, int n4) {
    int idx = blockIdx.x * blockDim.x + threadIdx.x;
    if (idx < n4) {
        float4 gv = g[idx], uv = u[idx];
        gv.x = f2tff(gv.x / (1.0f + __expf(-gv.x)) * uv.x);
        gv.y = f2tff(gv.y / (1.0f + __expf(-gv.y)) * uv.y);
        gv.z = f2tff(gv.z / (1.0f + __expf(-gv.z)) * uv.z);
        gv.w = f2tff(gv.w / (1.0f + __expf(-gv.w)) * uv.w);
        g[idx] = gv;
    }
}

// ---------------- TF32 tensor-core GEMM NT (cp.async 3-stage) ----------------
constexpr int GBM = 128, GBK = 32, GPAD = 4, GLDS = GBK + GPAD;
constexpr int GSTAGES = 3;
constexpr int ASTAGE  = GBM * GLDS;
#define GEMM_SMEM_BN(BN) (GSTAGES * (GBM + (BN)) * GLDS * 4)

// TRANSV: write C transposed as [col/128][row][col%128] (V into vals buffer)
template <int ADD, int BN, int TRANSV>
__device__ __forceinline__ void gemm_body(const float* __restrict__ A,
                                          const float* __restrict__ B,
                                          float* __restrict__ C,
                                          int N, int K, int m0, int n0,
                                          float* smem) {
    constexpr int NWN = BN / 16;       // n micro-tiles per warp
    constexpr int NTP = BN / 32;       // B ldmatrix groups
    constexpr int BSTAGE = BN * GLDS;  // floats per B stage
    float* sA = smem;
    float* sB = smem + GSTAGES * ASTAGE;

    const int tid = threadIdx.x, lane = tid & 31, wid = tid >> 5;
    const int wm = wid & 3, wn = wid >> 2;

    const int sr = tid >> 3;
    const int sc = (tid & 7) * 4;
    const float* Ag = A + (size_t)(m0 + sr) * K + sc;
    const float* Bg = B + (size_t)(n0 + sr) * K + sc;
    const uint32_t sAu = sptr(sA) + (sr * GLDS + sc) * 4;
    const uint32_t sBu = sptr(sB) + (sr * GLDS + sc) * 4;

    float acc[2][NWN][4];
#pragma unroll
    for (int i = 0; i < 2; i++)
#pragma unroll
        for (int j = 0; j < NWN; j++)
#pragma unroll
            for (int q = 0; q < 4; q++) acc[i][j][q] = 0.f;

    const int grp = lane >> 3, lr = lane & 7;
    const int a_row = wm * 32 + (grp & 1) * 8 + lr;
    const int a_col = (grp >> 1) * 4;
    const int b_row = wn * (BN / 2) + (grp >> 1) * 8 + lr;
    const int b_col = (grp & 1) * 4;

    const int nk = K / GBK;

    auto issue = [&](int stage, int kt) {
        const float* Ak = Ag + (size_t)kt * GBK;
        const float* Bk = Bg + (size_t)kt * GBK;
        uint32_t da = sAu + stage * (ASTAGE * 4);
        uint32_t db = sBu + stage * (BSTAGE * 4);
#pragma unroll
        for (int i = 0; i < 4; i++)
            cp_async16(da + i * (32 * GLDS * 4), Ak + (size_t)(32 * i) * K);
#pragma unroll
        for (int i = 0; i < BN / 32; i++)
            cp_async16(db + i * (32 * GLDS * 4), Bk + (size_t)(32 * i) * K);
        cp_commit();
    };

    issue(0, 0);
    if (nk > 1) issue(1, 1);

    for (int kt = 0; kt < nk; ++kt) {
        if (kt + 1 < nk) cp_wait<1>(); else cp_wait<0>();
        __syncthreads();
        const int cur = kt % GSTAGES;
        float* cA = sA + cur * ASTAGE;
        float* cB = sB + cur * BSTAGE;
        const uint32_t aaddr = sptr(cA + a_row * GLDS + a_col);
        const uint32_t baddr = sptr(cB + b_row * GLDS + b_col);
#pragma unroll
        for (int ks = 0; ks < 4; ++ks) {
            uint32_t af[2][4];
            ldm_x4(af[0], aaddr + ks * 32);
            ldm_x4(af[1], aaddr + 16 * GLDS * 4 + ks * 32);
            uint32_t bf[NTP][4];
#pragma unroll
            for (int ntp = 0; ntp < NTP; ++ntp)
                ldm_x4(bf[ntp], baddr + ntp * 16 * GLDS * 4 + ks * 32);
#pragma unroll
            for (int mt = 0; mt < 2; ++mt)
#pragma unroll
                for (int nt = 0; nt < NWN; ++nt)
                    mma_tf32(acc[mt][nt], af[mt], &bf[nt >> 1][(nt & 1) * 2]);
        }
        if (kt + 2 < nk) issue((kt + 2) % GSTAGES, kt + 2);
    }

    const int row0 = m0 + wm * 32 + (lane >> 2);
    const int col0 = n0 + wn * (BN / 2) + (lane & 3) * 2;
#pragma unroll
    for (int mt = 0; mt < 2; ++mt)
#pragma unroll
        for (int nt = 0; nt < NWN; ++nt) {
            int r = row0 + mt * 16;
            int c = col0 + nt * 8;
            float2 v0 = make_float2(acc[mt][nt][0], acc[mt][nt][1]);
            float2 v1 = make_float2(acc[mt][nt][2], acc[mt][nt][3]);
            if (TRANSV) {
                size_t i0 = ((size_t)(c >> 7) * Tn + r) * HDn + (c & 127);
                size_t i1 = ((size_t)(c >> 7) * Tn + (r + 8)) * HDn + (c & 127);
                *(float2*)&C[i0] = v0;
                *(float2*)&C[i1] = v1;
            } else {
                float2* p0 = (float2*)&C[(size_t)r * N + c];
                float2* p1 = (float2*)&C[(size_t)(r + 8) * N + c];
                if (ADD) {
                    float2 o0 = *p0, o1 = *p1;
                    v0.x += o0.x; v0.y += o0.y; v1.x += o1.x; v1.y += o1.y;
                }
                *p0 = v0;
                *p1 = v1;
            }
        }
}

template <int ADD, int BN>
__global__ __launch_bounds__(256, 2) void mma_nt_kernel(const float* __restrict__ A,
                                                        const float* __restrict__ B,
                                                        float* __restrict__ C,
                                                        int N, int K) {
    extern __shared__ float smem[];
    gemm_body<ADD, BN, 0>(A, B, C, N, K, blockIdx.y * GBM, blockIdx.x * BN, smem);
}

// fused QKV: grid.x = 16 (q) + 8 (k) + 8 (v); v written transposed into vals
__global__ __launch_bounds__(256, 2) void mma_qkv_kernel(const float* __restrict__ A,
                                                         const float* __restrict__ qw,
                                                         const float* __restrict__ kw,
                                                         const float* __restrict__ vw,
                                                         float* __restrict__ q,
                                                         float* __restrict__ k,
                                                         float* __restrict__ vlayer) {
    extern __shared__ float smem[];
    int bx = blockIdx.x;
    int m0 = blockIdx.y * GBM;
    if (bx < 16) {
        gemm_body<0, 128, 0>(A, qw, q, Hn * HDn, Dn, m0, bx * 128, smem);
    } else if (bx < 24) {
        gemm_body<0, 128, 0>(A, kw, k, KVn * HDn, Dn, m0, (bx - 16) * 128, smem);
    } else {
        gemm_body<0, 128, 1>(A, vw, vlayer, KVn * HDn, Dn, m0, (bx - 24) * 128, smem);
    }
}

// fused gate+up
__global__ __launch_bounds__(256, 2) void mma_gu_kernel(const float* __restrict__ A,
                                                        const float* __restrict__ gw,
                                                        const float* __restrict__ uw,
                                                        float* __restrict__ g,
                                                        float* __restrict__ u) {
    extern __shared__ float smem[];
    int bx = blockIdx.x;
    const float* B; float* C; int n0;
    if (bx < 24) { B = gw; C = g; n0 = bx * 128; }
    else         { B = uw; C = u; n0 = (bx - 24) * 128; }
    gemm_body<0, 128, 0>(A, B, C, FFn, Dn, blockIdx.y * GBM, n0, smem);
}

// ---------------- TF32 MMA flash attention: 128 q-rows, 8 warps ----------------
constexpr int A_KS = 132;
constexpr int A_VS = 68;
constexpr int A_PS = 68;
constexpr int ATTN_SMEM = (64 * A_KS + 128 * A_VS + 128 * A_PS) * 4;  // 103424

__global__ __launch_bounds__(256) void attn_mma_kernel(const float* __restrict__ Q,
                                                       const float* __restrict__ Kb,
                                                       const float* __restrict__ Vb,
                                                       float* __restrict__ O) {
    extern __shared__ float sm[];
    float* sK = sm;                     // [64][132]: Q staging chunks, then K tiles
    float* sV = sm + 64 * A_KS;         // [128][68]: V transposed (d-major)
    float* sP = sV + 128 * A_VS;        // [128][68]: P (per-warp 16-row slices)

    const int h = blockIdx.y;
    const int qt0 = (gridDim.x - 1 - blockIdx.x) * 128;  // heavy tiles first
    const int kv = h >> 1;
    const float scale = 0.0883883476483184f;
    const int tid = threadIdx.x, lane = tid & 31, wid = tid >> 5;
    const int grp = lane >> 3, lr = lane & 7;
    const int r0 = lane >> 2, c0 = (lane & 3) * 2;

    // ---- stage Q (scaled, tf32) in two 64-row chunks through sK ----
    uint32_t qf[16][4];
#pragma unroll
    for (int ch = 0; ch < 2; ++ch) {
        __syncthreads();
        const float* qb = Q + (size_t)(qt0 + ch * 64) * (Hn * HDn) + (size_t)h * HDn;
#pragma unroll
        for (int r = 0; r < 8; ++r) {
            int idx = tid + r * 256;
            int row = idx >> 5, c4 = idx & 31;
            float4 v = *(const float4*)(qb + (size_t)row * (Hn * HDn) + c4 * 4);
            uint4 u = make_uint4(f2tf(v.x * scale), f2tf(v.y * scale),
                                 f2tf(v.z * scale), f2tf(v.w * scale));
            *(uint4*)&sK[row * A_KS + c4 * 4] = u;
        }
        __syncthreads();
        if ((wid >> 2) == ch) {
            uint32_t qaddr = sptr(sK + ((wid & 3) * 16 + (grp & 1) * 8 + lr) * A_KS + (grp >> 1) * 4);
#pragma unroll
            for (int ks = 0; ks < 16; ++ks) ldm_x4(qf[ks], qaddr + ks * 32);
        }
    }
    __syncthreads();

    float o[16][4];
#pragma unroll
    for (int i = 0; i < 16; i++)
#pragma unroll
        for (int j = 0; j < 4; j++) o[i][j] = 0.f;
    float mreg[2] = {-1e30f, -1e30f}, lreg[2] = {0.f, 0.f};

    const float* Kh = Kb + (size_t)kv * Tn * HDn;
    const float* Vh = Vb + (size_t)kv * Tn * HDn;
    const int nkt = (qt0 >> 6) + 2;

    float* myP = sP + wid * 16 * A_PS;
    const uint32_t kaddr = sptr(sK + ((grp >> 1) * 8 + lr) * A_KS + (grp & 1) * 4);
    const uint32_t paddr = sptr(myP + ((grp & 1) * 8 + lr) * A_PS + (grp >> 1) * 4);
    const uint32_t vaddr = sptr(sV + ((grp >> 1) * 8 + lr) * A_VS + (grp & 1) * 4);

    for (int kt = 0; kt < nkt; ++kt) {
        const int kt0 = kt << 6;
        if (kt) __syncthreads();
        // stage K natural [kpos][d]
#pragma unroll
        for (int r = 0; r < 8; ++r) {
            int idx = tid + r * 256;
            int row = idx >> 5, c4 = idx & 31;
            float4 v = *(const float4*)(Kh + (size_t)(kt0 + row) * HDn + c4 * 4);
            uint4 u = make_uint4(f2tf(v.x), f2tf(v.y), f2tf(v.z), f2tf(v.w));
            *(uint4*)&sK[row * A_KS + c4 * 4] = u;
        }
        // stage V transposed [d][kpos]; 256 threads: 2 halves of kpos
        {
            const int d = tid & 127, half = tid >> 7;
#pragma unroll
            for (int rg = 0; rg < 8; ++rg) {
                int kp = half * 32 + rg * 4;
                float v0 = Vh[(size_t)(kt0 + kp + 0) * HDn + d];
                float v1 = Vh[(size_t)(kt0 + kp + 1) * HDn + d];
                float v2 = Vh[(size_t)(kt0 + kp + 2) * HDn + d];
                float v3 = Vh[(size_t)(kt0 + kp + 3) * HDn + d];
                uint4 u = make_uint4(f2tf(v0), f2tf(v1), f2tf(v2), f2tf(v3));
                *(uint4*)&sV[d * A_VS + kp] = u;
            }
        }
        __syncthreads();

        // ---- S = Q @ K^T (per warp: 16 rows x 64 cols) ----
        float s[8][4];
#pragma unroll
        for (int i = 0; i < 8; i++)
#pragma unroll
            for (int j = 0; j < 4; j++) s[i][j] = 0.f;
#pragma unroll
        for (int ks = 0; ks < 16; ++ks) {
            uint32_t bf[4][4];
#pragma unroll
            for (int ntp = 0; ntp < 4; ++ntp)
                ldm_x4(bf[ntp], kaddr + (ntp * 16 * A_KS) * 4 + ks * 32);
#pragma unroll
            for (int nt = 0; nt < 8; ++nt)
                mma_tf32(s[nt], qf[ks], &bf[nt >> 1][(nt & 1) * 2]);
        }

        // causal mask — only the last two k-tiles can intersect the diagonal
        if (kt >= nkt - 2) {
            int rowg = qt0 + wid * 16 + r0;
#pragma unroll
            for (int nt = 0; nt < 8; ++nt) {
                int colg = kt0 + nt * 8 + c0;
                if (colg > rowg)          s[nt][0] = -1e30f;
                if (colg + 1 > rowg)      s[nt][1] = -1e30f;
                if (colg > rowg + 8)      s[nt][2] = -1e30f;
                if (colg + 1 > rowg + 8)  s[nt][3] = -1e30f;
            }
        }

        // ---- online softmax ----
#pragma unroll
        for (int hf = 0; hf < 2; ++hf) {
            float rm = -1e30f;
#pragma unroll
            for (int nt = 0; nt < 8; ++nt)
                rm = fmaxf(rm, fmaxf(s[nt][2 * hf], s[nt][2 * hf + 1]));
            rm = fmaxf(rm, __shfl_xor_sync(0xffffffffu, rm, 1));
            rm = fmaxf(rm, __shfl_xor_sync(0xffffffffu, rm, 2));
            float mn = fmaxf(mreg[hf], rm);
            float corr = __expf(mreg[hf] - mn);
            mreg[hf] = mn;
            float su = 0.f;
#pragma unroll
            for (int nt = 0; nt < 8; ++nt) {
                float e0 = __expf(s[nt][2 * hf] - mn);
                float e1 = __expf(s[nt][2 * hf + 1] - mn);
                s[nt][2 * hf] = e0;
                s[nt][2 * hf + 1] = e1;
                su += e0 + e1;
            }
            su += __shfl_xor_sync(0xffffffffu, su, 1);
            su += __shfl_xor_sync(0xffffffffu, su, 2);
            lreg[hf] = lreg[hf] * corr + su;
#pragma unroll
            for (int nt = 0; nt < 16; ++nt) {
                o[nt][2 * hf] *= corr;
                o[nt][2 * hf + 1] *= corr;
            }
        }

        // ---- P to warp-private smem (tf32) ----
#pragma unroll
        for (int nt = 0; nt < 8; ++nt) {
            *(uint2*)&myP[r0 * A_PS + nt * 8 + c0] =
                make_uint2(f2tf(s[nt][0]), f2tf(s[nt][1]));
            *(uint2*)&myP[(r0 + 8) * A_PS + nt * 8 + c0] =
                make_uint2(f2tf(s[nt][2]), f2tf(s[nt][3]));
        }
        __syncwarp();

        // ---- O += P @ V ----
#pragma unroll
        for (int ks = 0; ks < 8; ++ks) {
            uint32_t pf[4];
            ldm_x4(pf, paddr + ks * 32);
#pragma unroll
            for (int np = 0; np < 8; ++np) {
                uint32_t bf[4];
                ldm_x4(bf, vaddr + (np * 16 * A_VS) * 4 + ks * 32);
                mma_tf32(o[2 * np],     pf, &bf[0]);
                mma_tf32(o[2 * np + 1], pf, &bf[2]);
            }
        }
    }

    // ---- epilogue: tf32-rounded (feeds O-projection via cp.async) ----
    float inv0 = 1.0f / lreg[0], inv1 = 1.0f / lreg[1];
    int rowg = qt0 + wid * 16 + r0;
#pragma unroll
    for (int nt = 0; nt < 16; ++nt) {
        size_t base = (size_t)h * HDn + nt * 8 + c0;
        *(float2*)&O[(size_t)rowg * (Hn * HDn) + base] =
            make_float2(f2tff(o[nt][0] * inv0), f2tff(o[nt][1] * inv0));
        *(float2*)&O[(size_t)(rowg + 8) * (Hn * HDn) + base] =
            make_float2(f2tff(o[nt][2] * inv1), f2tff(o[nt][3] * inv1));
    }
}

// ---------------- host orchestration ----------------
extern "C" void kernel_launch(void* const* d_in, const int* in_sizes, int n_in,
                              void* d_out, int out_size) {
    const float* emb = (const float*)d_in[0];
    const float* ln1 = (const float*)d_in[1];
    const float* qw  = (const float*)d_in[2];
    const float* kw  = (const float*)d_in[3];
    const float* vw  = (const float*)d_in[4];
    const float* qn  = (const float*)d_in[5];
    const float* kn  = (const float*)d_in[6];
    const float* ow  = (const float*)d_in[7];
    const float* ln2 = (const float*)d_in[8];
    const float* gw  = (const float*)d_in[9];
    const float* uw  = (const float*)d_in[10];
    const float* dw  = (const float*)d_in[11];
    const float* nw  = (const float*)d_in[12];

    float* out  = (float*)d_out;
    float* keys = out + (size_t)Tn * Dn;
    float* vals = keys + (size_t)Ln * KVn * Tn * HDn;

    float *ph, *px, *pq, *pao, *pkt, *pg, *pu, *pwc;
    cudaGetSymbolAddress((void**)&ph,  g_h);
    cudaGetSymbolAddress((void**)&px,  g_x);
    cudaGetSymbolAddress((void**)&pq,  g_q);
    cudaGetSymbolAddress((void**)&pao, g_ao);
    cudaGetSymbolAddress((void**)&pkt, g_kt);
    cudaGetSymbolAddress((void**)&pg,  g_gate);
    cudaGetSymbolAddress((void**)&pu,  g_up);
    cudaGetSymbolAddress((void**)&pwc, g_wc);

    cudaFuncSetAttribute(attn_mma_kernel, cudaFuncAttributeMaxDynamicSharedMemorySize, ATTN_SMEM);
    cudaFuncSetAttribute(mma_nt_kernel<1, 64>, cudaFuncAttributeMaxDynamicSharedMemorySize, GEMM_SMEM_BN(64));
    cudaFuncSetAttribute(mma_qkv_kernel, cudaFuncAttributeMaxDynamicSharedMemorySize, GEMM_SMEM_BN(128));
    cudaFuncSetAttribute(mma_gu_kernel, cudaFuncAttributeMaxDynamicSharedMemorySize, GEMM_SMEM_BN(128));

    // pre-round all weights to tf32, one kernel
    {
        Cv7 a;
        size_t offs[7] = { W_Q, W_K, W_V, W_O, W_G, W_U, W_D };
        const float* srcs[7] = { qw, kw, vw, ow, gw, uw, dw };
        size_t ns[7] = {
            (size_t)Ln * Hn * HDn * Dn, (size_t)Ln * KVn * HDn * Dn,
            (size_t)Ln * KVn * HDn * Dn, (size_t)Ln * Dn * Hn * HDn,
            (size_t)Ln * FFn * Dn, (size_t)Ln * FFn * Dn, (size_t)Ln * Dn * FFn };
        int cum = 0;
        for (int i = 0; i < 7; i++) {
            a.s[i] = (const float4*)srcs[i];
            a.d[i] = (float4*)(pwc + offs[i]);
            a.cum[i] = cum;
            cum += (int)(ns[i] / 4);
        }
        a.cum[7] = cum;
        conv7_kernel<<<(cum + 255) / 256, 256>>>(a);
    }

    cudaMemcpyAsync(ph, emb, sizeof(float) * Tn * Dn, cudaMemcpyDeviceToDevice);
    rope_tables_kernel<<<Tn, 64>>>();

    for (int i = 0; i < Ln; ++i) {
        float* klayer = keys + (size_t)i * KVn * Tn * HDn;
        float* vlayer = vals + (size_t)i * KVn * Tn * HDn;

        rms_rows_kernel<1><<<Tn, 256>>>(ph, ln1 + (size_t)i * Dn, px);

        mma_qkv_kernel<<<dim3(32, Tn / GBM), 256, GEMM_SMEM_BN(128)>>>(
            px, pwc + W_Q + (size_t)i * (Hn * HDn) * Dn,
            pwc + W_K + (size_t)i * (KVn * HDn) * Dn,
            pwc + W_V + (size_t)i * (KVn * HDn) * Dn, pq, pkt, vlayer);

        qknorm_rope_kernel<<<dim3(Tn, Hn + KVn), 128>>>(
            pq, pkt, klayer, qn + (size_t)i * HDn, kn + (size_t)i * HDn);

        attn_mma_kernel<<<dim3(Tn / 128, Hn), 256, ATTN_SMEM>>>(pq, klayer, vlayer, pao);

        mma_nt_kernel<1, 64><<<dim3(Dn / 64, Tn / GBM), 256, GEMM_SMEM_BN(64)>>>(
            pao, pwc + W_O + (size_t)i * Dn * (Hn * HDn), ph, Dn, Hn * HDn);

        rms_rows_kernel<1><<<Tn, 256>>>(ph, ln2 + (size_t)i * Dn, px);
        mma_gu_kernel<<<dim3(48, Tn / GBM), 256, GEMM_SMEM_BN(128)>>>(
            px, pwc + W_G + (size_t)i * FFn * Dn, pwc + W_U + (size_t)i * FFn * Dn, pg, pu);
        silu_mul_kernel<<<(Tn * FFn / 4) / 256, 256>>>((float4*)pg, (const float4*)pu, Tn * FFn / 4);
        mma_nt_kernel<1, 64><<<dim3(Dn / 64, Tn / GBM), 256, GEMM_SMEM_BN(64)>>>(
            pg, pwc + W_D + (size_t)i * Dn * FFn, ph, Dn, FFn);
    }

    rms_rows_kernel<0><<<Tn, 256>>>(ph, nw, out);
}

// round 9
// speedup vs baseline: 7.3410x; 1.5344x over previous
#include <cuda_runtime.h>
#include <cuda_fp16.h>
#include <math.h>
#include <stdint.h>

constexpr int Tn = 2048, Dn = 1024, Hn = 16, KVn = 8, HDn = 128, FFn = 3072, Ln = 5;
constexpr float EPSf = 1e-6f;

// ---------------- scratch ----------------
__device__ float g_h [Tn * Dn];
__device__ float g_q [Tn * Hn * HDn];
__device__ float g_kt[Tn * KVn * HDn];
__device__ float g_gate[Tn * FFn];
__device__ float g_up  [Tn * FFn];
__device__ float g_cos[Tn * 64];
__device__ float g_sin[Tn * 64];

__device__ __align__(16) __half g_xh [Tn * Dn];        // rms output (fp16)
__device__ __align__(16) __half g_aoh[Tn * Hn * HDn];  // attention output (fp16)
__device__ __align__(16) __half g_gh [Tn * FFn];       // silu(g)*u (fp16)

// fp16 weight arena
constexpr size_t W_Q  = 0;
constexpr size_t W_K  = W_Q + (size_t)Ln * Hn * HDn * Dn;
constexpr size_t W_V  = W_K + (size_t)Ln * KVn * HDn * Dn;
constexpr size_t W_O  = W_V + (size_t)Ln * KVn * HDn * Dn;
constexpr size_t W_G  = W_O + (size_t)Ln * Dn * Hn * HDn;
constexpr size_t W_U  = W_G + (size_t)Ln * FFn * Dn;
constexpr size_t W_D  = W_U + (size_t)Ln * FFn * Dn;
constexpr size_t W_TOT= W_D + (size_t)Ln * Dn * FFn;
__device__ __align__(16) __half g_w[W_TOT];

// ---------------- PTX helpers ----------------
__device__ __forceinline__ uint32_t sptr(const void* p) {
    return (uint32_t)__cvta_generic_to_shared(p);
}
__device__ __forceinline__ void ldm_x4(uint32_t* r, uint32_t addr) {
    asm volatile("ldmatrix.sync.aligned.m8n8.x4.shared.b16 {%0,%1,%2,%3}, [%4];"
                 : "=r"(r[0]), "=r"(r[1]), "=r"(r[2]), "=r"(r[3]) : "r"(addr));
}
__device__ __forceinline__ void mma_f16(float* c, const uint32_t* a, uint32_t b0, uint32_t b1) {
    asm volatile("mma.sync.aligned.m16n8k16.row.col.f32.f16.f16.f32 "
                 "{%0,%1,%2,%3}, {%4,%5,%6,%7}, {%8,%9}, {%0,%1,%2,%3};"
                 : "+f"(c[0]), "+f"(c[1]), "+f"(c[2]), "+f"(c[3])
                 : "r"(a[0]), "r"(a[1]), "r"(a[2]), "r"(a[3]), "r"(b0), "r"(b1));
}
__device__ __forceinline__ void cp_async16(uint32_t dst, const void* src) {
    asm volatile("cp.async.ca.shared.global [%0], [%1], 16;" :: "r"(dst), "l"(src));
}
__device__ __forceinline__ void cp_commit() {
    asm volatile("cp.async.commit_group;" ::: "memory");
}
template <int N>
__device__ __forceinline__ void cp_wait() {
    asm volatile("cp.async.wait_group %0;" :: "n"(N) : "memory");
}
__device__ __forceinline__ uint32_t h2u(__half2 h) { return *(uint32_t*)&h; }

// ---------------- weight fp16 conversion (7 segments, 1 kernel) ----------------
struct Cv7 {
    const float4* s[7];
    __half* d[7];
    int cum[8];
};
__global__ void conv7_kernel(Cv7 a) {
    int idx = blockIdx.x * 256 + threadIdx.x;
    if (idx >= a.cum[7]) return;
    int s = 0;
#pragma unroll
    for (int i = 0; i < 6; i++) s += (idx >= a.cum[i + 1]) ? 1 : 0;
    int off = idx - a.cum[s];
    float4 v = a.s[s][off];
    uint2 o = make_uint2(h2u(__floats2half2_rn(v.x, v.y)),
                         h2u(__floats2half2_rn(v.z, v.w)));
    ((uint2*)a.d[s])[off] = o;
}

// ---------------- RoPE tables ----------------
__global__ void rope_tables_kernel() {
    int t = blockIdx.x, j = threadIdx.x;
    float inv = 1.0f / powf(1.0e6f, (float)j * (1.0f / 64.0f));
    g_cos[t * 64 + j] = cosf((float)t * inv);
    g_sin[t * 64 + j] = sinf((float)t * inv);
}

// ---------------- RMSNorm rows (HALF: emit fp16; else fp32) ----------------
template <int HALF>
__global__ void rms_rows_kernel(const float* __restrict__ in,
                                const float* __restrict__ w,
                                float* __restrict__ out,
                                __half* __restrict__ oh) {
    int t = blockIdx.x;
    const float4* ip = (const float4*)(in + (size_t)t * Dn);
    const float4* wp = (const float4*)w;
    float4 v = ip[threadIdx.x];
    float s = v.x * v.x + v.y * v.y + v.z * v.z + v.w * v.w;
#pragma unroll
    for (int off = 16; off; off >>= 1) s += __shfl_xor_sync(0xffffffffu, s, off);
    __shared__ float ws[8];
    if ((threadIdx.x & 31) == 0) ws[threadIdx.x >> 5] = s;
    __syncthreads();
    float tot = 0.f;
#pragma unroll
    for (int i = 0; i < 8; i++) tot += ws[i];
    float r = rsqrtf(tot * (1.0f / (float)Dn) + EPSf);
    float4 wv = wp[threadIdx.x];
    float4 o = make_float4(v.x * r * wv.x, v.y * r * wv.y, v.z * r * wv.z, v.w * r * wv.w);
    if (HALF) {
        uint2 p = make_uint2(h2u(__floats2half2_rn(o.x, o.y)),
                             h2u(__floats2half2_rn(o.z, o.w)));
        ((uint2*)(oh + (size_t)t * Dn))[threadIdx.x] = p;
    } else {
        ((float4*)(out + (size_t)t * Dn))[threadIdx.x] = o;
    }
}

// ---------------- combined Q/K per-head RMSNorm + RoPE (fp32 in/out) ----------------
__global__ void qknorm_rope_kernel(float* __restrict__ q,
                                   const float* __restrict__ k,
                                   float* __restrict__ ko,
                                   const float* __restrict__ qw,
                                   const float* __restrict__ kw) {
    int t = blockIdx.x, h = blockIdx.y, d = threadIdx.x;
    bool isq = h < Hn;
    const float* row = isq ? (q + ((size_t)t * Hn + h) * HDn)
                           : (k + ((size_t)t * KVn + (h - Hn)) * HDn);
    const float* w = isq ? qw : kw;
    float v = row[d];
    float s = v * v;
#pragma unroll
    for (int off = 16; off; off >>= 1) s += __shfl_xor_sync(0xffffffffu, s, off);
    __shared__ float ws[4];
    if ((d & 31) == 0) ws[d >> 5] = s;
    __syncthreads();
    float r = rsqrtf((ws[0] + ws[1] + ws[2] + ws[3]) * (1.0f / (float)HDn) + EPSf);
    float xn = v * r * w[d];
    __shared__ float sh[128];
    sh[d] = xn;
    __syncthreads();
    float other = (d < 64) ? -sh[d + 64] : sh[d - 64];
    int j = d & 63;
    float o = xn * g_cos[t * 64 + j] + other * g_sin[t * 64 + j];
    if (isq) q[((size_t)t * Hn + h) * HDn + d] = o;
    else     ko[((size_t)(h - Hn) * Tn + t) * HDn + d] = o;
}

// ---------------- silu(g)*u -> fp16 ----------------
__global__ void silu_mul_kernel(const float4* __restrict__ g, const float4* __restrict__ u,
                                __half* __restrict__ oh, int n4) {
    int idx = blockIdx.x * blockDim.x + threadIdx.x;
    if (idx < n4) {
        float4 gv = g[idx], uv = u[idx];
        float r0 = gv.x / (1.0f + __expf(-gv.x)) * uv.x;
        float r1 = gv.y / (1.0f + __expf(-gv.y)) * uv.y;
        float r2 = gv.z / (1.0f + __expf(-gv.z)) * uv.z;
        float r3 = gv.w / (1.0f + __expf(-gv.w)) * uv.w;
        ((uint2*)oh)[idx] = make_uint2(h2u(__floats2half2_rn(r0, r1)),
                                       h2u(__floats2half2_rn(r2, r3)));
    }
}

// ---------------- fp16 tensor-core GEMM NT: C[M,N] (+)= A[M,K] * B[N,K]^T ----------------
// BM=128, BK=64 halves (128B rows, padded to 144B), 3 stages, 256 threads, 8 warps (4Mx2N).
constexpr int HROWB = 144;                    // padded row bytes
constexpr int ASTB  = 128 * HROWB;            // A stage bytes (18432)
#define HG_SMEM(BN) (3 * (128 + (BN)) * HROWB)

template <int ADD, int BN, int TRANSV>
__device__ __forceinline__ void hgemm_body(const __half* __restrict__ A,
                                           const __half* __restrict__ B,
                                           float* __restrict__ C,
                                           int N, int K, int m0, int n0,
                                           char* smem) {
    constexpr int BSTB = BN * HROWB;
    constexpr int NT2  = BN / 32;   // B ldmatrix groups per warp (warp n = BN/2)
    const int tid = threadIdx.x, lane = tid & 31, wid = tid >> 5;
    const int wm = wid & 3, wn = wid >> 2;

    const __half* Ag = A + (size_t)m0 * K;
    const __half* Bg = B + (size_t)n0 * K;
    const uint32_t sA = sptr(smem);
    const uint32_t sB = sA + 3 * ASTB;

    float acc[2][BN / 16][4];
#pragma unroll
    for (int i = 0; i < 2; i++)
#pragma unroll
        for (int j = 0; j < BN / 16; j++)
#pragma unroll
            for (int q = 0; q < 4; q++) acc[i][j][q] = 0.f;

    const int frow = ((lane >> 3) & 1) * 8 + (lane & 7);
    const int fcol = (lane >> 4) * 16;
    const int nk = K >> 6;

    auto stage = [&](int st, int kt) {
        const __half* Ak = Ag + (size_t)kt * 64;
        const __half* Bk = Bg + (size_t)kt * 64;
        uint32_t da = sA + st * ASTB;
        uint32_t db = sB + st * BSTB;
#pragma unroll
        for (int it = 0; it < 4; ++it) {
            int ch = tid + it * 256;
            int row = ch >> 3, c16 = ch & 7;
            cp_async16(da + row * HROWB + c16 * 16, Ak + (size_t)row * K + c16 * 8);
        }
#pragma unroll
        for (int it = 0; it < BN / 32; ++it) {
            int ch = tid + it * 256;
            int row = ch >> 3, c16 = ch & 7;
            cp_async16(db + row * HROWB + c16 * 16, Bk + (size_t)row * K + c16 * 8);
        }
        cp_commit();
    };

    stage(0, 0);
    if (nk > 1) stage(1, 1);

    for (int i = 0; i < nk; ++i) {
        if (i + 1 < nk) cp_wait<1>(); else cp_wait<0>();
        __syncthreads();
        const int cur = i % 3;
        const uint32_t aaddr = sA + cur * ASTB + (wm * 32 + frow) * HROWB + fcol;
        const uint32_t baddr = sB + cur * BSTB + (wn * (BN / 2) + frow) * HROWB + fcol;
#pragma unroll
        for (int ks = 0; ks < 4; ++ks) {
            uint32_t af[2][4];
            ldm_x4(af[0], aaddr + ks * 32);
            ldm_x4(af[1], aaddr + 16 * HROWB + ks * 32);
#pragma unroll
            for (int nt2 = 0; nt2 < NT2; ++nt2) {
                uint32_t bf[4];
                ldm_x4(bf, baddr + nt2 * 16 * HROWB + ks * 32);
#pragma unroll
                for (int mt = 0; mt < 2; ++mt) {
                    mma_f16(acc[mt][nt2 * 2],     af[mt], bf[0], bf[2]);
                    mma_f16(acc[mt][nt2 * 2 + 1], af[mt], bf[1], bf[3]);
                }
            }
        }
        if (i + 2 < nk) stage((i + 2) % 3, i + 2);
    }

    const int row0 = m0 + wm * 32 + (lane >> 2);
    const int col0 = n0 + wn * (BN / 2) + (lane & 3) * 2;
#pragma unroll
    for (int mt = 0; mt < 2; ++mt)
#pragma unroll
        for (int nt = 0; nt < BN / 16; ++nt) {
            int r = row0 + mt * 16;
            int c = col0 + nt * 8;
            float2 v0 = make_float2(acc[mt][nt][0], acc[mt][nt][1]);
            float2 v1 = make_float2(acc[mt][nt][2], acc[mt][nt][3]);
            if (TRANSV) {
                *(float2*)&C[((size_t)(c >> 7) * Tn + r) * HDn + (c & 127)] = v0;
                *(float2*)&C[((size_t)(c >> 7) * Tn + (r + 8)) * HDn + (c & 127)] = v1;
            } else {
                float2* p0 = (float2*)&C[(size_t)r * N + c];
                float2* p1 = (float2*)&C[(size_t)(r + 8) * N + c];
                if (ADD) {
                    float2 o0 = *p0, o1 = *p1;
                    v0.x += o0.x; v0.y += o0.y; v1.x += o1.x; v1.y += o1.y;
                }
                *p0 = v0;
                *p1 = v1;
            }
        }
}

// fused QKV: grid.x = 16 (q) + 8 (k) + 8 (v transposed into vals)
__global__ __launch_bounds__(256) void hg_qkv_kernel(
    const __half* __restrict__ xh,
    const __half* __restrict__ wq, const __half* __restrict__ wk, const __half* __restrict__ wv,
    float* __restrict__ q, float* __restrict__ k, float* __restrict__ vlayer) {
    extern __shared__ char smem[];
    int bx = blockIdx.x, m0 = blockIdx.y * 128;
    if (bx < 16)
        hgemm_body<0, 128, 0>(xh, wq, q, Hn * HDn, Dn, m0, bx * 128, smem);
    else if (bx < 24)
        hgemm_body<0, 128, 0>(xh, wk, k, KVn * HDn, Dn, m0, (bx - 16) * 128, smem);
    else
        hgemm_body<0, 128, 1>(xh, wv, vlayer, KVn * HDn, Dn, m0, (bx - 24) * 128, smem);
}

// fused gate+up: grid.x = 24 + 24
__global__ __launch_bounds__(256) void hg_gu_kernel(
    const __half* __restrict__ xh,
    const __half* __restrict__ wg, const __half* __restrict__ wu,
    float* __restrict__ g, float* __restrict__ u) {
    extern __shared__ char smem[];
    int bx = blockIdx.x, m0 = blockIdx.y * 128;
    if (bx < 24)
        hgemm_body<0, 128, 0>(xh, wg, g, FFn, Dn, m0, bx * 128, smem);
    else
        hgemm_body<0, 128, 0>(xh, wu, u, FFn, Dn, m0, (bx - 24) * 128, smem);
}

// residual-add GEMM (O-proj, down-proj), BN=64 for 256-CTA grids
__global__ __launch_bounds__(256, 2) void hg_add_kernel(
    const __half* __restrict__ a, const __half* __restrict__ b,
    float* __restrict__ C, int N, int K) {
    extern __shared__ char smem[];
    hgemm_body<1, 64, 0>(a, b, C, N, K, blockIdx.y * 128, blockIdx.x * 64, smem);
}

// ---------------- fp16 MMA flash attention: 128 q-rows, 8 warps ----------------
constexpr int SKH = 136;  // sK row stride (halves), 272B
constexpr int SVH = 72;   // sV row stride (halves), 144B
constexpr int SPH = 72;   // sP row stride
constexpr int ATTN_SMEM = (64 * SKH + 128 * SVH + 128 * SPH) * 2;  // 54272

__global__ __launch_bounds__(256) void attn_h_kernel(const float* __restrict__ Q,
                                                     const float* __restrict__ Kb,
                                                     const float* __restrict__ Vb,
                                                     __half* __restrict__ AO) {
    extern __shared__ char smraw[];
    __half* sK = (__half*)smraw;                 // [64][136]: Q staging, then K tiles
    __half* sV = sK + 64 * SKH;                  // [128][72]: V transposed (d-major)
    __half* sP = sV + 128 * SVH;                 // [128][72]: P per-warp slices

    const int h = blockIdx.y;
    const int qt0 = (gridDim.x - 1 - blockIdx.x) * 128;  // heavy tiles first
    const int kv = h >> 1;
    const float scale = 0.0883883476483184f;
    const int tid = threadIdx.x, lane = tid & 31, wid = tid >> 5;
    const int frow = ((lane >> 3) & 1) * 8 + (lane & 7);
    const int fcol = (lane >> 4) * 16;
    const int r0 = lane >> 2, c0 = (lane & 3) * 2;

    // ---- stage Q (scaled, fp16) in two 64-row chunks through sK; grab fragments ----
    uint32_t qf[8][4];
#pragma unroll
    for (int ch = 0; ch < 2; ++ch) {
        __syncthreads();
        const float* qb = Q + (size_t)(qt0 + ch * 64) * (Hn * HDn) + (size_t)h * HDn;
#pragma unroll
        for (int r = 0; r < 8; ++r) {
            int idx = tid + r * 256;
            int row = idx >> 5, c4 = idx & 31;
            float4 v = *(const float4*)(qb + (size_t)row * (Hn * HDn) + c4 * 4);
            *(uint2*)&sK[row * SKH + c4 * 4] =
                make_uint2(h2u(__floats2half2_rn(v.x * scale, v.y * scale)),
                           h2u(__floats2half2_rn(v.z * scale, v.w * scale)));
        }
        __syncthreads();
        if ((wid >> 2) == ch) {
            uint32_t qaddr = sptr(sK) + ((wid & 3) * 16 + frow) * (SKH * 2) + fcol;
#pragma unroll
            for (int ks = 0; ks < 8; ++ks) ldm_x4(qf[ks], qaddr + ks * 32);
        }
    }
    __syncthreads();

    float o[16][4];
#pragma unroll
    for (int i = 0; i < 16; i++)
#pragma unroll
        for (int j = 0; j < 4; j++) o[i][j] = 0.f;
    float mreg[2] = {-1e30f, -1e30f}, lreg[2] = {0.f, 0.f};

    const float* Kh = Kb + (size_t)kv * Tn * HDn;
    const float* Vh = Vb + (size_t)kv * Tn * HDn;
    const int nkt = (qt0 >> 6) + 2;

    __half* myP = sP + wid * 16 * SPH;
    const uint32_t kaddr = sptr(sK) + frow * (SKH * 2) + fcol;
    const uint32_t paddr = sptr(myP) + frow * (SPH * 2) + fcol;
    const uint32_t vaddr = sptr(sV) + frow * (SVH * 2) + fcol;

    for (int kt = 0; kt < nkt; ++kt) {
        const int kt0 = kt << 6;
        if (kt) __syncthreads();
        // stage K natural [kpos][d] fp16
#pragma unroll
        for (int r = 0; r < 8; ++r) {
            int idx = tid + r * 256;
            int row = idx >> 5, c4 = idx & 31;
            float4 v = *(const float4*)(Kh + (size_t)(kt0 + row) * HDn + c4 * 4);
            *(uint2*)&sK[row * SKH + c4 * 4] =
                make_uint2(h2u(__floats2half2_rn(v.x, v.y)),
                           h2u(__floats2half2_rn(v.z, v.w)));
        }
        // stage V transposed [d][kpos] fp16
        {
            const int d = tid & 127, half_ = tid >> 7;
#pragma unroll
            for (int rg = 0; rg < 8; ++rg) {
                int kp = half_ * 32 + rg * 4;
                float v0 = Vh[(size_t)(kt0 + kp + 0) * HDn + d];
                float v1 = Vh[(size_t)(kt0 + kp + 1) * HDn + d];
                float v2 = Vh[(size_t)(kt0 + kp + 2) * HDn + d];
                float v3 = Vh[(size_t)(kt0 + kp + 3) * HDn + d];
                *(uint2*)&sV[d * SVH + kp] =
                    make_uint2(h2u(__floats2half2_rn(v0, v1)),
                               h2u(__floats2half2_rn(v2, v3)));
            }
        }
        __syncthreads();

        // ---- S = Q @ K^T (per warp: 16 rows x 64 cols), 8 k16-steps ----
        float s[8][4];
#pragma unroll
        for (int i = 0; i < 8; i++)
#pragma unroll
            for (int j = 0; j < 4; j++) s[i][j] = 0.f;
#pragma unroll
        for (int ks = 0; ks < 8; ++ks) {
#pragma unroll
            for (int ntp = 0; ntp < 4; ++ntp) {
                uint32_t bf[4];
                ldm_x4(bf, kaddr + ntp * 16 * (SKH * 2) + ks * 32);
                mma_f16(s[ntp * 2],     qf[ks], bf[0], bf[2]);
                mma_f16(s[ntp * 2 + 1], qf[ks], bf[1], bf[3]);
            }
        }

        // causal mask — last two k-tiles only
        if (kt >= nkt - 2) {
            int rowg = qt0 + wid * 16 + r0;
#pragma unroll
            for (int nt = 0; nt < 8; ++nt) {
                int colg = kt0 + nt * 8 + c0;
                if (colg > rowg)          s[nt][0] = -1e30f;
                if (colg + 1 > rowg)      s[nt][1] = -1e30f;
                if (colg > rowg + 8)      s[nt][2] = -1e30f;
                if (colg + 1 > rowg + 8)  s[nt][3] = -1e30f;
            }
        }

        // ---- online softmax ----
#pragma unroll
        for (int hf = 0; hf < 2; ++hf) {
            float rm = -1e30f;
#pragma unroll
            for (int nt = 0; nt < 8; ++nt)
                rm = fmaxf(rm, fmaxf(s[nt][2 * hf], s[nt][2 * hf + 1]));
            rm = fmaxf(rm, __shfl_xor_sync(0xffffffffu, rm, 1));
            rm = fmaxf(rm, __shfl_xor_sync(0xffffffffu, rm, 2));
            float mn = fmaxf(mreg[hf], rm);
            float corr = __expf(mreg[hf] - mn);
            mreg[hf] = mn;
            float su = 0.f;
#pragma unroll
            for (int nt = 0; nt < 8; ++nt) {
                float e0 = __expf(s[nt][2 * hf] - mn);
                float e1 = __expf(s[nt][2 * hf + 1] - mn);
                s[nt][2 * hf] = e0;
                s[nt][2 * hf + 1] = e1;
                su += e0 + e1;
            }
            su += __shfl_xor_sync(0xffffffffu, su, 1);
            su += __shfl_xor_sync(0xffffffffu, su, 2);
            lreg[hf] = lreg[hf] * corr + su;
#pragma unroll
            for (int nt = 0; nt < 16; ++nt) {
                o[nt][2 * hf] *= corr;
                o[nt][2 * hf + 1] *= corr;
            }
        }

        // ---- P (fp16) to warp-private smem ----
#pragma unroll
        for (int nt = 0; nt < 8; ++nt) {
            *(__half2*)&myP[r0 * SPH + nt * 8 + c0] = __floats2half2_rn(s[nt][0], s[nt][1]);
            *(__half2*)&myP[(r0 + 8) * SPH + nt * 8 + c0] = __floats2half2_rn(s[nt][2], s[nt][3]);
        }
        __syncwarp();

        // ---- O += P @ V (4 k16-steps) ----
#pragma unroll
        for (int ks = 0; ks < 4; ++ks) {
            uint32_t pf[4];
            ldm_x4(pf, paddr + ks * 32);
#pragma unroll
            for (int np = 0; np < 8; ++np) {
                uint32_t bf[4];
                ldm_x4(bf, vaddr + np * 16 * (SVH * 2) + ks * 32);
                mma_f16(o[2 * np],     pf, bf[0], bf[2]);
                mma_f16(o[2 * np + 1], pf, bf[1], bf[3]);
            }
        }
    }

    // ---- epilogue: fp16 (feeds O-projection GEMM) ----
    float inv0 = 1.0f / lreg[0], inv1 = 1.0f / lreg[1];
    int rowg = qt0 + wid * 16 + r0;
#pragma unroll
    for (int nt = 0; nt < 16; ++nt) {
        size_t base = (size_t)h * HDn + nt * 8 + c0;
        *(__half2*)&AO[(size_t)rowg * (Hn * HDn) + base] =
            __floats2half2_rn(o[nt][0] * inv0, o[nt][1] * inv0);
        *(__half2*)&AO[(size_t)(rowg + 8) * (Hn * HDn) + base] =
            __floats2half2_rn(o[nt][2] * inv1, o[nt][3] * inv1);
    }
}

// ---------------- host orchestration ----------------
extern "C" void kernel_launch(void* const* d_in, const int* in_sizes, int n_in,
                              void* d_out, int out_size) {
    const float* emb = (const float*)d_in[0];
    const float* ln1 = (const float*)d_in[1];
    const float* qw  = (const float*)d_in[2];
    const float* kw  = (const float*)d_in[3];
    const float* vw  = (const float*)d_in[4];
    const float* qn  = (const float*)d_in[5];
    const float* kn  = (const float*)d_in[6];
    const float* ow  = (const float*)d_in[7];
    const float* ln2 = (const float*)d_in[8];
    const float* gw  = (const float*)d_in[9];
    const float* uw  = (const float*)d_in[10];
    const float* dw  = (const float*)d_in[11];
    const float* nw  = (const float*)d_in[12];

    float* out  = (float*)d_out;
    float* keys = out + (size_t)Tn * Dn;
    float* vals = keys + (size_t)Ln * KVn * Tn * HDn;

    float *ph, *pq, *pkt, *pg, *pu;
    __half *pxh, *paoh, *pgh, *pw;
    cudaGetSymbolAddress((void**)&ph,   g_h);
    cudaGetSymbolAddress((void**)&pq,   g_q);
    cudaGetSymbolAddress((void**)&pkt,  g_kt);
    cudaGetSymbolAddress((void**)&pg,   g_gate);
    cudaGetSymbolAddress((void**)&pu,   g_up);
    cudaGetSymbolAddress((void**)&pxh,  g_xh);
    cudaGetSymbolAddress((void**)&paoh, g_aoh);
    cudaGetSymbolAddress((void**)&pgh,  g_gh);
    cudaGetSymbolAddress((void**)&pw,   g_w);

    cudaFuncSetAttribute(attn_h_kernel, cudaFuncAttributeMaxDynamicSharedMemorySize, ATTN_SMEM);
    cudaFuncSetAttribute(hg_qkv_kernel, cudaFuncAttributeMaxDynamicSharedMemorySize, HG_SMEM(128));
    cudaFuncSetAttribute(hg_gu_kernel,  cudaFuncAttributeMaxDynamicSharedMemorySize, HG_SMEM(128));
    cudaFuncSetAttribute(hg_add_kernel, cudaFuncAttributeMaxDynamicSharedMemorySize, HG_SMEM(64));

    // convert all weights to fp16, one kernel
    {
        Cv7 a;
        size_t offs[7] = { W_Q, W_K, W_V, W_O, W_G, W_U, W_D };
        const float* srcs[7] = { qw, kw, vw, ow, gw, uw, dw };
        size_t ns[7] = {
            (size_t)Ln * Hn * HDn * Dn, (size_t)Ln * KVn * HDn * Dn,
            (size_t)Ln * KVn * HDn * Dn, (size_t)Ln * Dn * Hn * HDn,
            (size_t)Ln * FFn * Dn, (size_t)Ln * FFn * Dn, (size_t)Ln * Dn * FFn };
        int cum = 0;
        for (int i = 0; i < 7; i++) {
            a.s[i] = (const float4*)srcs[i];
            a.d[i] = pw + offs[i];
            a.cum[i] = cum;
            cum += (int)(ns[i] / 4);
        }
        a.cum[7] = cum;
        conv7_kernel<<<(cum + 255) / 256, 256>>>(a);
    }

    cudaMemcpyAsync(ph, emb, sizeof(float) * Tn * Dn, cudaMemcpyDeviceToDevice);
    rope_tables_kernel<<<Tn, 64>>>();

    for (int i = 0; i < Ln; ++i) {
        float* klayer = keys + (size_t)i * KVn * Tn * HDn;
        float* vlayer = vals + (size_t)i * KVn * Tn * HDn;

        rms_rows_kernel<1><<<Tn, 256>>>(ph, ln1 + (size_t)i * Dn, nullptr, pxh);

        hg_qkv_kernel<<<dim3(32, Tn / 128), 256, HG_SMEM(128)>>>(
            pxh,
            pw + W_Q + (size_t)i * (Hn * HDn) * Dn,
            pw + W_K + (size_t)i * (KVn * HDn) * Dn,
            pw + W_V + (size_t)i * (KVn * HDn) * Dn,
            pq, pkt, vlayer);

        qknorm_rope_kernel<<<dim3(Tn, Hn + KVn), 128>>>(
            pq, pkt, klayer, qn + (size_t)i * HDn, kn + (size_t)i * HDn);

        attn_h_kernel<<<dim3(Tn / 128, Hn), 256, ATTN_SMEM>>>(pq, klayer, vlayer, paoh);

        hg_add_kernel<<<dim3(Dn / 64, Tn / 128), 256, HG_SMEM(64)>>>(
            paoh, pw + W_O + (size_t)i * Dn * (Hn * HDn), ph, Dn, Hn * HDn);

        rms_rows_kernel<1><<<Tn, 256>>>(ph, ln2 + (size_t)i * Dn, nullptr, pxh);

        hg_gu_kernel<<<dim3(48, Tn / 128), 256, HG_SMEM(128)>>>(
            pxh,
            pw + W_G + (size_t)i * FFn * Dn,
            pw + W_U + (size_t)i * FFn * Dn,
            pg, pu);

        silu_mul_kernel<<<(Tn * FFn / 4 + 255) / 256, 256>>>(
            (const float4*)pg, (const float4*)pu, pgh, Tn * FFn / 4);

        hg_add_kernel<<<dim3(Dn / 64, Tn / 128), 256, HG_SMEM(64)>>>(
            pgh, pw + W_D + (size_t)i * Dn * FFn, ph, Dn, FFn);
    }

    rms_rows_kernel<0><<<Tn, 256>>>(ph, nw, out, nullptr);
}